// round 12
// baseline (speedup 1.0000x reference)
#include <cuda_runtime.h>
#include <cuda_bf16.h>
#include <math.h>
#include <stdint.h>

#define EPSV 1e-5f
constexpr int Bb=64, NN=46656, F0=147, E1=1024, LL=36, H1=1024, H2=256, EMP=148;
constexpr int NPAD=46720;   // 365*128

__device__ float g_T2[108*H1];          // pair tables, b1 folded into p=0
__device__ float g_b2f[H2];
__device__ float g_b3f[16];
__device__ float g_s1[Bb];
__device__ float g_e1[Bb*E1];
__device__ __nv_bfloat16 g_W2nh[H2*H1];   // [o][j], bn2-scaled hi
__device__ __nv_bfloat16 g_W2nl[H2*H1];
__device__ __nv_bfloat16 g_W1nh[784*H2];  // [p'=hw*16+ch][i], bn3-scaled hi
__device__ __nv_bfloat16 g_W1nl[784*H2];
__device__ __nv_bfloat16 g_A2h[(size_t)NPAD*288];  // padded MMA layout: [row][kc*72+off]
__device__ __nv_bfloat16 g_A2l[(size_t)NPAD*288];
__device__ float g_em[(size_t)NPAD*EMP];  // col 147 stays 0

__device__ __forceinline__ void bsplit(float v,__nv_bfloat16&hi,__nv_bfloat16&lo){
    hi=__float2bfloat16(v); lo=__float2bfloat16(v-__bfloat162float(hi));
}
__device__ __forceinline__ void mma16816(float* c,const uint32_t* a,uint32_t b0,uint32_t b1){
    asm volatile("mma.sync.aligned.m16n8k16.row.col.f32.bf16.bf16.f32 "
        "{%0,%1,%2,%3},{%4,%5,%6,%7},{%8,%9},{%0,%1,%2,%3};"
        :"+f"(c[0]),"+f"(c[1]),"+f"(c[2]),"+f"(c[3])
        :"r"(a[0]),"r"(a[1]),"r"(a[2]),"r"(a[3]),"r"(b0),"r"(b1));
}
__device__ __forceinline__ uint32_t pack2(float va,float vb){
    uint32_t hp; asm("cvt.rn.bf16x2.f32 %0,%1,%2;":"=r"(hp):"f"(vb),"f"(va)); return hp;
}
__device__ __forceinline__ void cp16(void* dst,const void* src){
    uint32_t d; asm("{ .reg .u64 t; cvta.to.shared.u64 t, %1; cvt.u32.u64 %0, t; }":"=r"(d):"l"(dst));
    asm volatile("cp.async.cg.shared.global [%0], [%1], 16;"::"r"(d),"l"(src):"memory");
}
#define CP_COMMIT() asm volatile("cp.async.commit_group;":::"memory")
#define CP_WAIT0()  asm volatile("cp.async.wait_group 0;":::"memory")

// ------------------- k_prep: direct pair tables + weights + x stats -------------------
__global__ void k_prep(
    const float* __restrict__ x,
    const float* __restrict__ embeds,const float* __restrict__ dfc1_w,
    const float* __restrict__ dfc1_b,const float* __restrict__ g1,const float* __restrict__ be1,
    const float* __restrict__ rm1,const float* __restrict__ rv1,
    const float* __restrict__ dfc2_w,const float* __restrict__ dfc2_b,
    const float* __restrict__ g2,const float* __restrict__ be2,
    const float* __restrict__ rm2,const float* __restrict__ rv2,
    const float* __restrict__ dct1_w,const float* __restrict__ dct1_b,
    const float* __restrict__ g3,const float* __restrict__ be3,
    const float* __restrict__ rm3,const float* __restrict__ rv3){
    int stride=gridDim.x*blockDim.x, tid=blockIdx.x*blockDim.x+threadIdx.x;
    // pair tables directly: T2[p*36+a*6+b][j] = a1*(e_{2p,a}.w_{2p} + e_{2p+1,b}.w_{2p+1}) (+b1' if p==0)
    for(int i=tid;i<108*H1;i+=stride){
        int m=i>>10, j=i&1023;
        int p=m/36, ab=m%36, a=ab/6, b=ab%6;
        const float* ea=embeds+((p*2)*6+a)*32;
        const float* eb=embeds+((p*2+1)*6+b)*32;
        const float* wa=dfc1_w+(size_t)j*192+(p*2)*32;
        const float* wb=wa+32;
        float s=0.f;
#pragma unroll
        for(int d=0;d<32;d++) s+=ea[d]*wa[d]+eb[d]*wb[d];
        float a1=g1[j]*rsqrtf(rv1[j]+EPSV);
        float v=a1*s;
        if(p==0) v+=a1*(dfc1_b[j]-rm1[j])+be1[j];
        g_T2[i]=v;
    }
    for(int i=tid;i<H2*H1;i+=stride){
        int o=i>>10;
        float a=g2[o]*rsqrtf(rv2[o]+EPSV);
        __nv_bfloat16 hi,lo; bsplit(a*dfc2_w[i],hi,lo);
        g_W2nh[i]=hi; g_W2nl[i]=lo;
    }
    for(int o=tid;o<H2;o+=stride){
        float a=g2[o]*rsqrtf(rv2[o]+EPSV);
        g_b2f[o]=a*(dfc2_b[o]-rm2[o])+be2[o];
    }
    for(int e=tid;e<784*H2;e+=stride){
        int pcol=e>>8, i=e&255, hw=pcol>>4, ch=pcol&15;
        float a=g3[ch]*rsqrtf(rv3[ch]+EPSV);
        __nv_bfloat16 hi,lo; bsplit(a*dct1_w[i*784+ch*49+hw],hi,lo);
        g_W1nh[e]=hi; g_W1nl[e]=lo;
    }
    for(int o=tid;o<16;o+=stride){
        float a=g3[o]*rsqrtf(rv3[o]+EPSV);
        g_b3f[o]=a*(dct1_b[o]-rm3[o])+be3[o];
    }
    for(int b=tid;b<Bb;b+=stride){
        float s=0.f;
        for(int r=0;r<F0;r++){float v=x[b*F0+r];s+=v*v;}
        g_s1[b]=s;
    }
}

// ------------------- GEMM1 (blocks 0-728) + encoder chain (block 729) -----------------
constexpr int G1_T=0, G1_AH=1024, G1_AL=G1_AH+9216, G1_BH=G1_AL+9216, G1_BL=G1_BH+36864;
constexpr int G1_SME=G1_BL+36864;   // 93184 B
__global__ void __launch_bounds__(256,2)
k_gemm1(const float* __restrict__ x,
        const float* __restrict__ conv_w,const float* __restrict__ conv_b,
        const float* __restrict__ eg2,const float* __restrict__ eb2,
        const float* __restrict__ fc1_w,const float* __restrict__ fc1_b,
        const float* __restrict__ eg1,const float* __restrict__ eb1,
        const float* __restrict__ fc2_w,const float* __restrict__ fc2_b,
        float* __restrict__ dist_out,float* __restrict__ loss_out){
    extern __shared__ char sm[];
    const int t=threadIdx.x;
    if(blockIdx.x==729){
        // ---------- fused encoder chain, hidden under gemm1 ----------
        float* e0=(float*)sm;               // [r][b] layout: e0[r*64+b], 64KB
        float* lg=(float*)(sm+65536);       // 64*36 logits
        __shared__ float red[4][2];
        int jl=t>>6, b=t&63, wh=(t>>5)&1;
        const float* xb=x+(size_t)b*F0;
        // enc1: 256 outputs, 4 at a time
        for(int jg=0;jg<64;jg++){
            int j=jg*4+jl;
            const float* wj=conv_w+(size_t)j*F0;
            float s=conv_b[j];
            for(int r=0;r<F0;r++) s+=xb[r]*__ldg(wj+r);
            float p=s;
            for(int o=16;o;o>>=1) p+=__shfl_xor_sync(0xffffffffu,p,o);
            if((t&31)==0) red[jl][wh]=p;
            __syncthreads();
            float m=(red[jl][0]+red[jl][1])*(1.f/64.f);
            __syncthreads();
            float d=s-m; p=d*d;
            for(int o=16;o;o>>=1) p+=__shfl_xor_sync(0xffffffffu,p,o);
            if((t&31)==0) red[jl][wh]=p;
            __syncthreads();
            float var=(red[jl][0]+red[jl][1])*(1.f/64.f);
            e0[j*64+b]=fmaxf(eg2[j]*d*rsqrtf(var+EPSV)+eb2[j],0.f);
            __syncthreads();
        }
        // enc2: 1024 outputs, 4 at a time; e0 read [r][b] (conflict-free per warp)
        for(int jg=0;jg<256;jg++){
            int j=jg*4+jl;
            const float* wj=fc1_w+(size_t)j*256;
            float s=fc1_b[j];
#pragma unroll 8
            for(int r=0;r<256;r++) s+=e0[r*64+b]*__ldg(wj+r);
            float p=s;
            for(int o=16;o;o>>=1) p+=__shfl_xor_sync(0xffffffffu,p,o);
            if((t&31)==0) red[jl][wh]=p;
            __syncthreads();
            float m=(red[jl][0]+red[jl][1])*(1.f/64.f);
            __syncthreads();
            float d=s-m; p=d*d;
            for(int o=16;o;o>>=1) p+=__shfl_xor_sync(0xffffffffu,p,o);
            if((t&31)==0) red[jl][wh]=p;
            __syncthreads();
            float var=(red[jl][0]+red[jl][1])*(1.f/64.f);
            g_e1[(size_t)b*E1+j]=fmaxf(eg1[j]*d*rsqrtf(var+EPSV)+eb1[j],0.f);
            __syncthreads();
        }
        // enc_head
        for(int d=t;d<Bb*LL;d+=256){
            int bb=d/LL, l=d%LL;
            const float4* wl=(const float4*)(fc2_w+(size_t)l*E1);
            const float4* e=(const float4*)(g_e1+(size_t)bb*E1);
            float s=fc2_b[l];
#pragma unroll 8
            for(int j=0;j<256;j++){
                float4 a=e[j], c=__ldg(wl+j);
                s+=a.x*c.x+a.y*c.y+a.z*c.z+a.w*c.w;
            }
            lg[d]=s;
        }
        __syncthreads();
        if(t<Bb){
            const float* l=lg+t*LL;
            float loss=0.f;
            for(int v=0;v<6;v++){
                float mx=-1e30f;
                for(int k=0;k<6;k++) mx=fmaxf(mx,l[v*6+k]);
                float ex[6],se=0.f;
                for(int k=0;k<6;k++){ex[k]=expf(l[v*6+k]-mx);se+=ex[k];}
                float inv=1.f/se;
                for(int k=0;k<6;k++){
                    float pp=ex[k]*inv;
                    dist_out[t*LL+v*6+k]=pp;
                    loss+=pp*logf(pp+1e-10f);
                }
            }
            loss_out[t]=0.1f*loss;
        }
        return;
    }
    // ---------- GEMM1 core (round-8/11 exact) ----------
    int* tb=(int*)(sm+G1_T);
    const int wid=t>>5, lane=t&31, gid=lane>>2, tig=lane&3;
    const int n0=blockIdx.x*64;
    if(t<192){
        int r=t/3, c=t-r*3, n=n0+r;
        int val=(c==0)? (n/1296)%36 : (c==1)? 36+(n/36)%36 : 72+n%36;
        tb[t]=val*H1;
    }
    float acc[64];
#pragma unroll
    for(int i=0;i<64;i++) acc[i]=0.f;
    const int mrow0=(wid&3)*16, ncol0=(wid>>2)*128;

    for(int kc=0;kc<16;kc++){
        __syncthreads();
        const int kb=kc*64;
#pragma unroll
        for(int i=0;i<8;i++){
            int u=i*256+t, row=u>>3, part=u&7;
            cp16(sm+G1_BH+row*144+part*16,(const char*)g_W2nh+(size_t)row*2048+kb*2+part*16);
            cp16(sm+G1_BL+row*144+part*16,(const char*)g_W2nl+(size_t)row*2048+kb*2+part*16);
        }
        CP_COMMIT();
#pragma unroll
        for(int i=0;i<8;i++){
            int e=i*256+t, r=e>>5, l2=(e&31)*2, j=kb+l2;
            const int* tr=tb+r*3;
            float2 s0=*(const float2*)(g_T2+tr[0]+j);
            float2 s1=*(const float2*)(g_T2+tr[1]+j);
            float2 s2=*(const float2*)(g_T2+tr[2]+j);
            float va=fmaxf(s0.x+s1.x+s2.x,0.f), vb=fmaxf(s0.y+s1.y+s2.y,0.f);
            uint32_t hp=pack2(va,vb);
            float la=va-__uint_as_float(hp<<16), lb=vb-__uint_as_float(hp&0xffff0000u);
            uint32_t lp=pack2(la,lb);
            *(uint32_t*)(sm+G1_AH+r*144+l2*2)=hp;
            *(uint32_t*)(sm+G1_AL+r*144+l2*2)=lp;
        }
        CP_WAIT0();
        __syncthreads();
#pragma unroll
        for(int ks=0;ks<4;ks++){
            int ao=(mrow0+gid)*144+ks*32+tig*4;
            uint32_t ah[4],al[4];
            ah[0]=*(const uint32_t*)(sm+G1_AH+ao);
            ah[1]=*(const uint32_t*)(sm+G1_AH+ao+1152);
            ah[2]=*(const uint32_t*)(sm+G1_AH+ao+16);
            ah[3]=*(const uint32_t*)(sm+G1_AH+ao+1168);
            al[0]=*(const uint32_t*)(sm+G1_AL+ao);
            al[1]=*(const uint32_t*)(sm+G1_AL+ao+1152);
            al[2]=*(const uint32_t*)(sm+G1_AL+ao+16);
            al[3]=*(const uint32_t*)(sm+G1_AL+ao+1168);
#pragma unroll
            for(int g=0;g<16;g++){
                int bo=(ncol0+g*8+gid)*144+ks*32+tig*4;
                uint32_t bh0=*(const uint32_t*)(sm+G1_BH+bo);
                uint32_t bh1=*(const uint32_t*)(sm+G1_BH+bo+16);
                uint32_t bl0=*(const uint32_t*)(sm+G1_BL+bo);
                uint32_t bl1=*(const uint32_t*)(sm+G1_BL+bo+16);
                float* c=acc+g*4;
                mma16816(c,ah,bh0,bh1);
                mma16816(c,ah,bl0,bl1);
                mma16816(c,al,bh0,bh1);
            }
        }
    }
    const int r0=n0+mrow0+gid;
#pragma unroll
    for(int nt=0;nt<16;nt++){
        int col=ncol0+nt*8+tig*2;
        float ba=g_b2f[col], bb2=g_b2f[col+1];
        size_t base=(size_t)(col>>6)*144+(col&63)*2;
        float v00=fmaxf(acc[nt*4+0]+ba,0.f), v01=fmaxf(acc[nt*4+1]+bb2,0.f);
        float v10=fmaxf(acc[nt*4+2]+ba,0.f), v11=fmaxf(acc[nt*4+3]+bb2,0.f);
        uint32_t hp=pack2(v00,v01);
        float la=v00-__uint_as_float(hp<<16), lb=v01-__uint_as_float(hp&0xffff0000u);
        *(uint32_t*)((char*)g_A2h+(size_t)r0*576+base)=hp;
        *(uint32_t*)((char*)g_A2l+(size_t)r0*576+base)=pack2(la,lb);
        hp=pack2(v10,v11);
        la=v10-__uint_as_float(hp<<16); lb=v11-__uint_as_float(hp&0xffff0000u);
        *(uint32_t*)((char*)g_A2h+(size_t)(r0+8)*576+base)=hp;
        *(uint32_t*)((char*)g_A2l+(size_t)(r0+8)*576+base)=pack2(la,lb);
    }
}

// ------------------- GEMM2: round-8/11 exact (grid (365,2)) -------------------
constexpr int G2_BH0=0, G2_BL0=16128, G2_BH1=32256, G2_BL1=48384;
constexpr int G2_SME=64512;
__global__ void __launch_bounds__(256,2)
k_gemm2(const float* __restrict__ dct2_w,const float* __restrict__ dct2_b){
    extern __shared__ char sm[];
    const int t=threadIdx.x, wid=t>>5, lane=t&31, gid=lane>>2, tig=lane&3;
    const int n0=blockIdx.x*128;
    const int s0=blockIdx.y, scnt=blockIdx.y? 3:4;
    float wv[12], b3v[4], dbv[3];
    {
        int ch0=tig*2;
        int chs[4]={ch0,ch0+1,8+ch0,9+ch0};
#pragma unroll
        for(int q=0;q<4;q++){
            b3v[q]=g_b3f[chs[q]];
#pragma unroll
            for(int o=0;o<3;o++) wv[q*3+o]=dct2_w[chs[q]*3+o];
        }
#pragma unroll
        for(int o=0;o<3;o++) dbv[o]=dct2_b[o];
    }
    const int row0=n0+wid*16+gid, row1=row0+8;
    const char* A2h=(const char*)g_A2h;
    const char* A2l=(const char*)g_A2l;

#define G2_STAGE(S,KC,BUF) do{ \
    int _bh=(BUF)? G2_BH1:G2_BH0, _bl=(BUF)? G2_BL1:G2_BL0; \
    _Pragma("unroll") \
    for(int _i=0;_i<7;_i++){ \
        int _u=_i*256+t; int _kind=_u>=896; int _uu=_kind? _u-896:_u; int _row=_uu>>3,_part=_uu&7; \
        const char* _src=(_kind? (const char*)g_W1nl:(const char*)g_W1nh)+(size_t)((S)*112+_row)*512+(KC)*128+_part*16; \
        cp16(sm+(_kind? _bl:_bh)+_row*144+_part*16,_src); \
    } CP_COMMIT(); }while(0)

    G2_STAGE(s0,0,0);
    CP_WAIT0();
    __syncthreads();
    int cc=0;
    for(int si=0;si<scnt;si++){
        int s=s0+si*2;
        float acc[56];
#pragma unroll
        for(int i=0;i<56;i++) acc[i]=0.f;
        for(int kc=0;kc<4;kc++){
            int buf=cc&1;
            if(cc+1<scnt*4){
                int nn=cc+1, s2=s0+(nn>>2)*2, kc2=nn&3;
                G2_STAGE(s2,kc2,buf^1);
            }
            int bh=buf? G2_BH1:G2_BH0, bl=buf? G2_BL1:G2_BL0;
#pragma unroll
            for(int ks=0;ks<4;ks++){
                size_t ao=(size_t)kc*144+(size_t)(ks*32+tig*4);
                uint32_t ah[4],al[4];
                ah[0]=*(const uint32_t*)(A2h+(size_t)row0*576+ao);
                ah[1]=*(const uint32_t*)(A2h+(size_t)row1*576+ao);
                ah[2]=*(const uint32_t*)(A2h+(size_t)row0*576+ao+16);
                ah[3]=*(const uint32_t*)(A2h+(size_t)row1*576+ao+16);
                al[0]=*(const uint32_t*)(A2l+(size_t)row0*576+ao);
                al[1]=*(const uint32_t*)(A2l+(size_t)row1*576+ao);
                al[2]=*(const uint32_t*)(A2l+(size_t)row0*576+ao+16);
                al[3]=*(const uint32_t*)(A2l+(size_t)row1*576+ao+16);
#pragma unroll
                for(int g=0;g<14;g++){
                    int bo=(g*8+gid)*144+ks*32+tig*4;
                    uint32_t bh0=*(const uint32_t*)(sm+bh+bo);
                    uint32_t bh1=*(const uint32_t*)(sm+bh+bo+16);
                    uint32_t bl0=*(const uint32_t*)(sm+bl+bo);
                    uint32_t bl1=*(const uint32_t*)(sm+bl+bo+16);
                    float* c=acc+g*4;
                    mma16816(c,ah,bh0,bh1);
                    mma16816(c,ah,bl0,bl1);
                    mma16816(c,al,bh0,bh1);
                }
            }
            CP_WAIT0();
            __syncthreads();
            cc++;
        }
#pragma unroll
        for(int hw=0;hw<7;hw++){
            float hA0=fmaxf(acc[hw*8+0]+b3v[0],0.f);
            float hA1=fmaxf(acc[hw*8+1]+b3v[1],0.f);
            float hB0=fmaxf(acc[hw*8+4]+b3v[2],0.f);
            float hB1=fmaxf(acc[hw*8+5]+b3v[3],0.f);
            float hC0=fmaxf(acc[hw*8+2]+b3v[0],0.f);
            float hC1=fmaxf(acc[hw*8+3]+b3v[1],0.f);
            float hD0=fmaxf(acc[hw*8+6]+b3v[2],0.f);
            float hD1=fmaxf(acc[hw*8+7]+b3v[3],0.f);
            float p[6];
#pragma unroll
            for(int o=0;o<3;o++){
                p[o]  =hA0*wv[o]+hA1*wv[3+o]+hB0*wv[6+o]+hB1*wv[9+o];
                p[3+o]=hC0*wv[o]+hC1*wv[3+o]+hD0*wv[6+o]+hD1*wv[9+o];
            }
#pragma unroll
            for(int off=1;off<4;off<<=1)
#pragma unroll
                for(int q=0;q<6;q++) p[q]+=__shfl_xor_sync(0xffffffffu,p[q],off);
            if(tig<3){
                g_em[(size_t)row0*EMP+tig*49+s*7+hw]=p[tig]+dbv[tig];
                g_em[(size_t)row1*EMP+tig*49+s*7+hw]=p[3+tig]+dbv[tig];
            }
        }
    }
#undef G2_STAGE
}

// ------------------- obs: ONB=96, occ 2 -------------------
constexpr int ONB=96;
constexpr int OBS_SMEM=(ONB*EMP+64*EMP+ONB+64)*4;
__global__ void __launch_bounds__(256,2)
k_obs(const float* __restrict__ x,float* __restrict__ obs){
    extern __shared__ float smf[];
    float* ems=smf;
    float* xs=ems+ONB*EMP;
    float* s2s=xs+64*EMP;
    float* s1s=s2s+ONB;
    const int t=threadIdx.x, n0=blockIdx.x*ONB;
    {
        float4* dst=(float4*)ems;
        const float4* src=(const float4*)(g_em+(size_t)n0*EMP);
        for(int id=t;id<ONB*(EMP/4);id+=256) dst[id]=__ldg(src+id);
    }
    for(int id=t;id<64*F0;id+=256){
        int r=id/F0, c=id-r*F0;
        xs[r*EMP+c]=x[id];
    }
    if(t<64){ xs[t*EMP+F0]=0.f; s1s[t]=g_s1[t]; }
    __syncthreads();
    if(t<ONB){
        const float4* e=(const float4*)(ems+t*EMP);
        float s=0.f;
#pragma unroll 4
        for(int r=0;r<EMP/4;r++){
            float4 v=e[r];
            s+=v.x*v.x+v.y*v.y+v.z*v.z+v.w*v.w;
        }
        s2s[t]=s;
    }
    __syncthreads();
#pragma unroll
    for(int jj=0;jj<2;jj++){
        int tt=t+jj*256;
        if(tt<384){
            int bt=tt/24, nt=tt%24;
            const float4* xp0=(const float4*)(xs+(bt*4+0)*EMP);
            const float4* xp1=(const float4*)(xs+(bt*4+1)*EMP);
            const float4* xp2=(const float4*)(xs+(bt*4+2)*EMP);
            const float4* xp3=(const float4*)(xs+(bt*4+3)*EMP);
            const float4* e0=(const float4*)(ems+(nt*4+0)*EMP);
            const float4* e1=(const float4*)(ems+(nt*4+1)*EMP);
            const float4* e2=(const float4*)(ems+(nt*4+2)*EMP);
            const float4* e3=(const float4*)(ems+(nt*4+3)*EMP);
            float a[16];
#pragma unroll
            for(int i=0;i<16;i++) a[i]=0.f;
            for(int r=0;r<EMP/4;r++){
                float4 xv[4]={xp0[r],xp1[r],xp2[r],xp3[r]};
                float4 ev[4]={e0[r],e1[r],e2[r],e3[r]};
#pragma unroll
                for(int i=0;i<4;i++)
#pragma unroll
                    for(int k=0;k<4;k++)
                        a[i*4+k]+=xv[i].x*ev[k].x+xv[i].y*ev[k].y+xv[i].z*ev[k].z+xv[i].w*ev[k].w;
            }
#pragma unroll
            for(int i=0;i<4;i++){
                int b=bt*4+i;
                float4 o;
                o.x=-0.5f*(s2s[nt*4+0]-2.f*a[i*4+0]+s1s[b]);
                o.y=-0.5f*(s2s[nt*4+1]-2.f*a[i*4+1]+s1s[b]);
                o.z=-0.5f*(s2s[nt*4+2]-2.f*a[i*4+2]+s1s[b]);
                o.w=-0.5f*(s2s[nt*4+3]-2.f*a[i*4+3]+s1s[b]);
                *(float4*)(obs+(size_t)b*NN+n0+nt*4)=o;
            }
        }
    }
}

// ------------------- launch (4 kernels) -------------------
extern "C" void kernel_launch(void* const* d_in,const int* in_sizes,int n_in,
                              void* d_out,int out_size){
    const float* x     =(const float*)d_in[0];
    const float* conv_w=(const float*)d_in[1];
    const float* conv_b=(const float*)d_in[2];
    const float* ebn2_g=(const float*)d_in[3];
    const float* ebn2_b=(const float*)d_in[4];
    const float* fc1_w =(const float*)d_in[5];
    const float* fc1_b =(const float*)d_in[6];
    const float* ebn1_g=(const float*)d_in[7];
    const float* ebn1_b=(const float*)d_in[8];
    const float* fc2_w =(const float*)d_in[9];
    const float* fc2_b =(const float*)d_in[10];
    const float* embeds=(const float*)d_in[11];
    const float* dfc1_w=(const float*)d_in[12];
    const float* dfc1_b=(const float*)d_in[13];
    const float* dbn1_g=(const float*)d_in[14];
    const float* dbn1_b=(const float*)d_in[15];
    const float* dbn1_rm=(const float*)d_in[16];
    const float* dbn1_rv=(const float*)d_in[17];
    const float* dfc2_w=(const float*)d_in[18];
    const float* dfc2_b=(const float*)d_in[19];
    const float* dbn2_g=(const float*)d_in[20];
    const float* dbn2_b=(const float*)d_in[21];
    const float* dbn2_rm=(const float*)d_in[22];
    const float* dbn2_rv=(const float*)d_in[23];
    const float* dct1_w=(const float*)d_in[24];
    const float* dct1_b=(const float*)d_in[25];
    const float* dbn3_g=(const float*)d_in[26];
    const float* dbn3_b=(const float*)d_in[27];
    const float* dbn3_rm=(const float*)d_in[28];
    const float* dbn3_rv=(const float*)d_in[29];
    const float* dct2_w=(const float*)d_in[30];
    const float* dct2_b=(const float*)d_in[31];

    float* out=(float*)d_out;
    float* obs=out;
    float* dist=out+(size_t)Bb*NN;
    float* loss=dist+(size_t)Bb*LL;

    cudaFuncSetAttribute(k_gemm1,cudaFuncAttributeMaxDynamicSharedMemorySize,G1_SME);
    cudaFuncSetAttribute(k_gemm2,cudaFuncAttributeMaxDynamicSharedMemorySize,G2_SME);
    cudaFuncSetAttribute(k_obs,cudaFuncAttributeMaxDynamicSharedMemorySize,OBS_SMEM);

    k_prep<<<256,256>>>(x,embeds,dfc1_w,dfc1_b,dbn1_g,dbn1_b,dbn1_rm,dbn1_rv,
                        dfc2_w,dfc2_b,dbn2_g,dbn2_b,dbn2_rm,dbn2_rv,
                        dct1_w,dct1_b,dbn3_g,dbn3_b,dbn3_rm,dbn3_rv);
    k_gemm1<<<730,256,G1_SME>>>(x,conv_w,conv_b,ebn2_g,ebn2_b,
                                fc1_w,fc1_b,ebn1_g,ebn1_b,fc2_w,fc2_b,dist,loss);
    k_gemm2<<<dim3(365,2),256,G2_SME>>>(dct2_w,dct2_b);
    k_obs<<<NN/ONB,256,OBS_SMEM>>>(x,obs);
}

// round 13
// speedup vs baseline: 5.0470x; 5.0470x over previous
#include <cuda_runtime.h>
#include <cuda_bf16.h>
#include <math.h>
#include <stdint.h>

#define EPSV 1e-5f
constexpr int Bb=64, NN=46656, F0=147, E1=1024, LL=36, H1=1024, H2=256, EMP=148;
constexpr int NPAD=46720;   // 365*128

__device__ float g_T2[108*H1];          // pair tables, b1 folded into p=0
__device__ float g_b2f[H2];
__device__ float g_b3f[16];
__device__ float g_s1[Bb];
__device__ float g_e0[Bb*256];
__device__ float g_e1[Bb*E1];
__device__ __nv_bfloat16 g_W2nh[H2*H1];   // [o][j], bn2-scaled hi
__device__ __nv_bfloat16 g_W2nl[H2*H1];
__device__ __nv_bfloat16 g_W1nh[784*H2];  // [p'=hw*16+ch][i], bn3-scaled hi
__device__ __nv_bfloat16 g_W1nl[784*H2];
__device__ __nv_bfloat16 g_A2h[(size_t)NPAD*288];  // padded MMA layout: [row][kc*72+off]
__device__ __nv_bfloat16 g_A2l[(size_t)NPAD*288];
__device__ float g_em[(size_t)NPAD*EMP];  // col 147 stays 0

__device__ __forceinline__ void bsplit(float v,__nv_bfloat16&hi,__nv_bfloat16&lo){
    hi=__float2bfloat16(v); lo=__float2bfloat16(v-__bfloat162float(hi));
}
__device__ __forceinline__ void mma16816(float* c,const uint32_t* a,uint32_t b0,uint32_t b1){
    asm volatile("mma.sync.aligned.m16n8k16.row.col.f32.bf16.bf16.f32 "
        "{%0,%1,%2,%3},{%4,%5,%6,%7},{%8,%9},{%0,%1,%2,%3};"
        :"+f"(c[0]),"+f"(c[1]),"+f"(c[2]),"+f"(c[3])
        :"r"(a[0]),"r"(a[1]),"r"(a[2]),"r"(a[3]),"r"(b0),"r"(b1));
}
__device__ __forceinline__ uint32_t pack2(float va,float vb){
    uint32_t hp; asm("cvt.rn.bf16x2.f32 %0,%1,%2;":"=r"(hp):"f"(vb),"f"(va)); return hp;
}
__device__ __forceinline__ void cp16(void* dst,const void* src){
    uint32_t d; asm("{ .reg .u64 t; cvta.to.shared.u64 t, %1; cvt.u32.u64 %0, t; }":"=r"(d):"l"(dst));
    asm volatile("cp.async.cg.shared.global [%0], [%1], 16;"::"r"(d),"l"(src):"memory");
}
#define CP_COMMIT() asm volatile("cp.async.commit_group;":::"memory")
#define CP_WAIT0()  asm volatile("cp.async.wait_group 0;":::"memory")

// ------------------- k_prep: direct pair tables + weights + x stats -------------------
__global__ void k_prep(
    const float* __restrict__ x,
    const float* __restrict__ embeds,const float* __restrict__ dfc1_w,
    const float* __restrict__ dfc1_b,const float* __restrict__ g1,const float* __restrict__ be1,
    const float* __restrict__ rm1,const float* __restrict__ rv1,
    const float* __restrict__ dfc2_w,const float* __restrict__ dfc2_b,
    const float* __restrict__ g2,const float* __restrict__ be2,
    const float* __restrict__ rm2,const float* __restrict__ rv2,
    const float* __restrict__ dct1_w,const float* __restrict__ dct1_b,
    const float* __restrict__ g3,const float* __restrict__ be3,
    const float* __restrict__ rm3,const float* __restrict__ rv3){
    int stride=gridDim.x*blockDim.x, tid=blockIdx.x*blockDim.x+threadIdx.x;
    for(int i=tid;i<108*H1;i+=stride){
        int m=i>>10, j=i&1023;
        int p=m/36, ab=m%36, a=ab/6, b=ab%6;
        const float* ea=embeds+((p*2)*6+a)*32;
        const float* eb=embeds+((p*2+1)*6+b)*32;
        const float* wa=dfc1_w+(size_t)j*192+(p*2)*32;
        const float* wb=wa+32;
        float s=0.f;
#pragma unroll
        for(int d=0;d<32;d++) s+=ea[d]*wa[d]+eb[d]*wb[d];
        float a1=g1[j]*rsqrtf(rv1[j]+EPSV);
        float v=a1*s;
        if(p==0) v+=a1*(dfc1_b[j]-rm1[j])+be1[j];
        g_T2[i]=v;
    }
    for(int i=tid;i<H2*H1;i+=stride){
        int o=i>>10;
        float a=g2[o]*rsqrtf(rv2[o]+EPSV);
        __nv_bfloat16 hi,lo; bsplit(a*dfc2_w[i],hi,lo);
        g_W2nh[i]=hi; g_W2nl[i]=lo;
    }
    for(int o=tid;o<H2;o+=stride){
        float a=g2[o]*rsqrtf(rv2[o]+EPSV);
        g_b2f[o]=a*(dfc2_b[o]-rm2[o])+be2[o];
    }
    for(int e=tid;e<784*H2;e+=stride){
        int pcol=e>>8, i=e&255, hw=pcol>>4, ch=pcol&15;
        float a=g3[ch]*rsqrtf(rv3[ch]+EPSV);
        __nv_bfloat16 hi,lo; bsplit(a*dct1_w[i*784+ch*49+hw],hi,lo);
        g_W1nh[e]=hi; g_W1nl[e]=lo;
    }
    for(int o=tid;o<16;o+=stride){
        float a=g3[o]*rsqrtf(rv3[o]+EPSV);
        g_b3f[o]=a*(dct1_b[o]-rm3[o])+be3[o];
    }
    for(int b=tid;b<Bb;b+=stride){
        float s=0.f;
        for(int r=0;r<F0;r++){float v=x[b*F0+r];s+=v*v;}
        g_s1[b]=s;
    }
}

// ------------------- encoder (round-11 exact) -------------------
__global__ void k_enc1(const float* __restrict__ x,const float* __restrict__ w,
                       const float* __restrict__ bias,
                       const float* __restrict__ gg,const float* __restrict__ bb){
    int t=threadIdx.x, jl=t>>6, b=t&63, j=blockIdx.x*4+jl;
    const float* wj=w+(size_t)j*F0;
    const float* xb=x+(size_t)b*F0;
    float s=bias[j];
    for(int r=0;r<F0;r++) s+=xb[r]*__ldg(wj+r);
    __shared__ float red[4][2];
    int wh=(t>>5)&1;
    float p=s;
    for(int o=16;o;o>>=1) p+=__shfl_xor_sync(0xffffffffu,p,o);
    if((t&31)==0) red[jl][wh]=p;
    __syncthreads();
    float m=(red[jl][0]+red[jl][1])*(1.f/64.f);
    __syncthreads();
    float d=s-m; p=d*d;
    for(int o=16;o;o>>=1) p+=__shfl_xor_sync(0xffffffffu,p,o);
    if((t&31)==0) red[jl][wh]=p;
    __syncthreads();
    float var=(red[jl][0]+red[jl][1])*(1.f/64.f);
    g_e0[b*256+j]=fmaxf(gg[j]*d*rsqrtf(var+EPSV)+bb[j],0.f);
}
__global__ void k_enc2(const float* __restrict__ w,const float* __restrict__ bias,
                       const float* __restrict__ gg,const float* __restrict__ bb){
    int t=threadIdx.x, jl=t>>6, b=t&63, j=blockIdx.x*4+jl;
    const float4* wj=(const float4*)(w+(size_t)j*256);
    const float4* xb=(const float4*)(g_e0+b*256);
    float s=bias[j];
#pragma unroll 8
    for(int r=0;r<64;r++){
        float4 a=xb[r], c=__ldg(wj+r);
        s+=a.x*c.x+a.y*c.y+a.z*c.z+a.w*c.w;
    }
    __shared__ float red[4][2];
    int wh=(t>>5)&1;
    float p=s;
    for(int o=16;o;o>>=1) p+=__shfl_xor_sync(0xffffffffu,p,o);
    if((t&31)==0) red[jl][wh]=p;
    __syncthreads();
    float m=(red[jl][0]+red[jl][1])*(1.f/64.f);
    __syncthreads();
    float d=s-m; p=d*d;
    for(int o=16;o;o>>=1) p+=__shfl_xor_sync(0xffffffffu,p,o);
    if((t&31)==0) red[jl][wh]=p;
    __syncthreads();
    float var=(red[jl][0]+red[jl][1])*(1.f/64.f);
    g_e1[(size_t)b*E1+j]=fmaxf(gg[j]*d*rsqrtf(var+EPSV)+bb[j],0.f);
}
__global__ void k_enc_head(const float* __restrict__ fc2_w,const float* __restrict__ fc2_b,
                           float* __restrict__ dist_out,float* __restrict__ loss_out){
    int b=blockIdx.x;
    __shared__ float es[E1];
    __shared__ float lg[LL];
    for(int j=threadIdx.x;j<E1;j+=blockDim.x) es[j]=g_e1[(size_t)b*E1+j];
    __syncthreads();
    if(threadIdx.x<LL){
        const float* w=fc2_w+(size_t)threadIdx.x*E1;
        float s=fc2_b[threadIdx.x];
        for(int j=0;j<E1;j++) s+=es[j]*__ldg(w+j);
        lg[threadIdx.x]=s;
    }
    __syncthreads();
    if(threadIdx.x==0){
        float loss=0.f;
        for(int v=0;v<6;v++){
            float mx=-1e30f;
            for(int k=0;k<6;k++) mx=fmaxf(mx,lg[v*6+k]);
            float ex[6],se=0.f;
            for(int k=0;k<6;k++){ex[k]=expf(lg[v*6+k]-mx);se+=ex[k];}
            float inv=1.f/se;
            for(int k=0;k<6;k++){
                float pp=ex[k]*inv;
                dist_out[b*LL+v*6+k]=pp;
                loss+=pp*logf(pp+1e-10f);
            }
        }
        loss_out[b]=0.1f*loss;
    }
}

// ------------------- GEMM1: round-8/11 exact -------------------
constexpr int G1_T=0, G1_AH=1024, G1_AL=G1_AH+9216, G1_BH=G1_AL+9216, G1_BL=G1_BH+36864;
constexpr int G1_SME=G1_BL+36864;   // 93184 B
__global__ void __launch_bounds__(256,2) k_gemm1(){
    extern __shared__ char sm[];
    int* tb=(int*)(sm+G1_T);
    const int t=threadIdx.x, wid=t>>5, lane=t&31, gid=lane>>2, tig=lane&3;
    const int n0=blockIdx.x*64;
    if(t<192){
        int r=t/3, c=t-r*3, n=n0+r;
        int val=(c==0)? (n/1296)%36 : (c==1)? 36+(n/36)%36 : 72+n%36;
        tb[t]=val*H1;
    }
    float acc[64];
#pragma unroll
    for(int i=0;i<64;i++) acc[i]=0.f;
    const int mrow0=(wid&3)*16, ncol0=(wid>>2)*128;

    for(int kc=0;kc<16;kc++){
        __syncthreads();
        const int kb=kc*64;
#pragma unroll
        for(int i=0;i<8;i++){
            int u=i*256+t, row=u>>3, part=u&7;
            cp16(sm+G1_BH+row*144+part*16,(const char*)g_W2nh+(size_t)row*2048+kb*2+part*16);
            cp16(sm+G1_BL+row*144+part*16,(const char*)g_W2nl+(size_t)row*2048+kb*2+part*16);
        }
        CP_COMMIT();
#pragma unroll
        for(int i=0;i<8;i++){
            int e=i*256+t, r=e>>5, l2=(e&31)*2, j=kb+l2;
            const int* tr=tb+r*3;
            float2 s0=*(const float2*)(g_T2+tr[0]+j);
            float2 s1=*(const float2*)(g_T2+tr[1]+j);
            float2 s2=*(const float2*)(g_T2+tr[2]+j);
            float va=fmaxf(s0.x+s1.x+s2.x,0.f), vb=fmaxf(s0.y+s1.y+s2.y,0.f);
            uint32_t hp=pack2(va,vb);
            float la=va-__uint_as_float(hp<<16), lb=vb-__uint_as_float(hp&0xffff0000u);
            uint32_t lp=pack2(la,lb);
            *(uint32_t*)(sm+G1_AH+r*144+l2*2)=hp;
            *(uint32_t*)(sm+G1_AL+r*144+l2*2)=lp;
        }
        CP_WAIT0();
        __syncthreads();
#pragma unroll
        for(int ks=0;ks<4;ks++){
            int ao=(mrow0+gid)*144+ks*32+tig*4;
            uint32_t ah[4],al[4];
            ah[0]=*(const uint32_t*)(sm+G1_AH+ao);
            ah[1]=*(const uint32_t*)(sm+G1_AH+ao+1152);
            ah[2]=*(const uint32_t*)(sm+G1_AH+ao+16);
            ah[3]=*(const uint32_t*)(sm+G1_AH+ao+1168);
            al[0]=*(const uint32_t*)(sm+G1_AL+ao);
            al[1]=*(const uint32_t*)(sm+G1_AL+ao+1152);
            al[2]=*(const uint32_t*)(sm+G1_AL+ao+16);
            al[3]=*(const uint32_t*)(sm+G1_AL+ao+1168);
#pragma unroll
            for(int g=0;g<16;g++){
                int bo=(ncol0+g*8+gid)*144+ks*32+tig*4;
                uint32_t bh0=*(const uint32_t*)(sm+G1_BH+bo);
                uint32_t bh1=*(const uint32_t*)(sm+G1_BH+bo+16);
                uint32_t bl0=*(const uint32_t*)(sm+G1_BL+bo);
                uint32_t bl1=*(const uint32_t*)(sm+G1_BL+bo+16);
                float* c=acc+g*4;
                mma16816(c,ah,bh0,bh1);
                mma16816(c,ah,bl0,bl1);
                mma16816(c,al,bh0,bh1);
            }
        }
    }
    const int r0=n0+mrow0+gid;
#pragma unroll
    for(int nt=0;nt<16;nt++){
        int col=ncol0+nt*8+tig*2;
        float ba=g_b2f[col], bb2=g_b2f[col+1];
        size_t base=(size_t)(col>>6)*144+(col&63)*2;
        float v00=fmaxf(acc[nt*4+0]+ba,0.f), v01=fmaxf(acc[nt*4+1]+bb2,0.f);
        float v10=fmaxf(acc[nt*4+2]+ba,0.f), v11=fmaxf(acc[nt*4+3]+bb2,0.f);
        uint32_t hp=pack2(v00,v01);
        float la=v00-__uint_as_float(hp<<16), lb=v01-__uint_as_float(hp&0xffff0000u);
        *(uint32_t*)((char*)g_A2h+(size_t)r0*576+base)=hp;
        *(uint32_t*)((char*)g_A2l+(size_t)r0*576+base)=pack2(la,lb);
        hp=pack2(v10,v11);
        la=v10-__uint_as_float(hp<<16); lb=v11-__uint_as_float(hp&0xffff0000u);
        *(uint32_t*)((char*)g_A2h+(size_t)(r0+8)*576+base)=hp;
        *(uint32_t*)((char*)g_A2l+(size_t)(r0+8)*576+base)=pack2(la,lb);
    }
}

// ------------------- GEMM2: round-8/11 exact (grid (365,2)) -------------------
constexpr int G2_BH0=0, G2_BL0=16128, G2_BH1=32256, G2_BL1=48384;
constexpr int G2_SME=64512;
__global__ void __launch_bounds__(256,2)
k_gemm2(const float* __restrict__ dct2_w,const float* __restrict__ dct2_b){
    extern __shared__ char sm[];
    const int t=threadIdx.x, wid=t>>5, lane=t&31, gid=lane>>2, tig=lane&3;
    const int n0=blockIdx.x*128;
    const int s0=blockIdx.y, scnt=blockIdx.y? 3:4;
    float wv[12], b3v[4], dbv[3];
    {
        int ch0=tig*2;
        int chs[4]={ch0,ch0+1,8+ch0,9+ch0};
#pragma unroll
        for(int q=0;q<4;q++){
            b3v[q]=g_b3f[chs[q]];
#pragma unroll
            for(int o=0;o<3;o++) wv[q*3+o]=dct2_w[chs[q]*3+o];
        }
#pragma unroll
        for(int o=0;o<3;o++) dbv[o]=dct2_b[o];
    }
    const int row0=n0+wid*16+gid, row1=row0+8;
    const char* A2h=(const char*)g_A2h;
    const char* A2l=(const char*)g_A2l;

#define G2_STAGE(S,KC,BUF) do{ \
    int _bh=(BUF)? G2_BH1:G2_BH0, _bl=(BUF)? G2_BL1:G2_BL0; \
    _Pragma("unroll") \
    for(int _i=0;_i<7;_i++){ \
        int _u=_i*256+t; int _kind=_u>=896; int _uu=_kind? _u-896:_u; int _row=_uu>>3,_part=_uu&7; \
        const char* _src=(_kind? (const char*)g_W1nl:(const char*)g_W1nh)+(size_t)((S)*112+_row)*512+(KC)*128+_part*16; \
        cp16(sm+(_kind? _bl:_bh)+_row*144+_part*16,_src); \
    } CP_COMMIT(); }while(0)

    G2_STAGE(s0,0,0);
    CP_WAIT0();
    __syncthreads();
    int cc=0;
    for(int si=0;si<scnt;si++){
        int s=s0+si*2;
        float acc[56];
#pragma unroll
        for(int i=0;i<56;i++) acc[i]=0.f;
        for(int kc=0;kc<4;kc++){
            int buf=cc&1;
            if(cc+1<scnt*4){
                int nn=cc+1, s2=s0+(nn>>2)*2, kc2=nn&3;
                G2_STAGE(s2,kc2,buf^1);
            }
            int bh=buf? G2_BH1:G2_BH0, bl=buf? G2_BL1:G2_BL0;
#pragma unroll
            for(int ks=0;ks<4;ks++){
                size_t ao=(size_t)kc*144+(size_t)(ks*32+tig*4);
                uint32_t ah[4],al[4];
                ah[0]=*(const uint32_t*)(A2h+(size_t)row0*576+ao);
                ah[1]=*(const uint32_t*)(A2h+(size_t)row1*576+ao);
                ah[2]=*(const uint32_t*)(A2h+(size_t)row0*576+ao+16);
                ah[3]=*(const uint32_t*)(A2h+(size_t)row1*576+ao+16);
                al[0]=*(const uint32_t*)(A2l+(size_t)row0*576+ao);
                al[1]=*(const uint32_t*)(A2l+(size_t)row1*576+ao);
                al[2]=*(const uint32_t*)(A2l+(size_t)row0*576+ao+16);
                al[3]=*(const uint32_t*)(A2l+(size_t)row1*576+ao+16);
#pragma unroll
                for(int g=0;g<14;g++){
                    int bo=(g*8+gid)*144+ks*32+tig*4;
                    uint32_t bh0=*(const uint32_t*)(sm+bh+bo);
                    uint32_t bh1=*(const uint32_t*)(sm+bh+bo+16);
                    uint32_t bl0=*(const uint32_t*)(sm+bl+bo);
                    uint32_t bl1=*(const uint32_t*)(sm+bl+bo+16);
                    float* c=acc+g*4;
                    mma16816(c,ah,bh0,bh1);
                    mma16816(c,ah,bl0,bl1);
                    mma16816(c,al,bh0,bh1);
                }
            }
            CP_WAIT0();
            __syncthreads();
            cc++;
        }
#pragma unroll
        for(int hw=0;hw<7;hw++){
            float hA0=fmaxf(acc[hw*8+0]+b3v[0],0.f);
            float hA1=fmaxf(acc[hw*8+1]+b3v[1],0.f);
            float hB0=fmaxf(acc[hw*8+4]+b3v[2],0.f);
            float hB1=fmaxf(acc[hw*8+5]+b3v[3],0.f);
            float hC0=fmaxf(acc[hw*8+2]+b3v[0],0.f);
            float hC1=fmaxf(acc[hw*8+3]+b3v[1],0.f);
            float hD0=fmaxf(acc[hw*8+6]+b3v[2],0.f);
            float hD1=fmaxf(acc[hw*8+7]+b3v[3],0.f);
            float p[6];
#pragma unroll
            for(int o=0;o<3;o++){
                p[o]  =hA0*wv[o]+hA1*wv[3+o]+hB0*wv[6+o]+hB1*wv[9+o];
                p[3+o]=hC0*wv[o]+hC1*wv[3+o]+hD0*wv[6+o]+hD1*wv[9+o];
            }
#pragma unroll
            for(int off=1;off<4;off<<=1)
#pragma unroll
                for(int q=0;q<6;q++) p[q]+=__shfl_xor_sync(0xffffffffu,p[q],off);
            if(tig<3){
                g_em[(size_t)row0*EMP+tig*49+s*7+hw]=p[tig]+dbv[tig];
                g_em[(size_t)row1*EMP+tig*49+s*7+hw]=p[3+tig]+dbv[tig];
            }
        }
    }
#undef G2_STAGE
}

// ------------------- obs: ONB=96, occ 2, 4x8 register tiles -------------------
constexpr int ONB=96;
constexpr int OBS_SMEM=(ONB*EMP+64*EMP+ONB+64)*4;
__global__ void __launch_bounds__(256,2)
k_obs(const float* __restrict__ x,float* __restrict__ obs){
    extern __shared__ float smf[];
    float* ems=smf;
    float* xs=ems+ONB*EMP;
    float* s2s=xs+64*EMP;
    float* s1s=s2s+ONB;
    const int t=threadIdx.x, n0=blockIdx.x*ONB;
    {
        float4* dst=(float4*)ems;
        const float4* src=(const float4*)(g_em+(size_t)n0*EMP);
        for(int id=t;id<ONB*(EMP/4);id+=256) dst[id]=__ldg(src+id);
    }
    for(int id=t;id<64*F0;id+=256){
        int r=id/F0, c=id-r*F0;
        xs[r*EMP+c]=x[id];
    }
    if(t<64){ xs[t*EMP+F0]=0.f; s1s[t]=g_s1[t]; }
    __syncthreads();
    if(t<ONB){
        const float4* e=(const float4*)(ems+t*EMP);
        float s=0.f;
#pragma unroll 4
        for(int r=0;r<EMP/4;r++){
            float4 v=e[r];
            s+=v.x*v.x+v.y*v.y+v.z*v.z+v.w*v.w;
        }
        s2s[t]=s;
    }
    __syncthreads();
    if(t<192){
        int bt=t/12, nt=t%12;      // 16 b-groups x 12 n-groups; tile 4b x 8n
        const float4* xp[4];
        const float4* ep[8];
#pragma unroll
        for(int i=0;i<4;i++) xp[i]=(const float4*)(xs+(bt*4+i)*EMP);
#pragma unroll
        for(int k=0;k<8;k++) ep[k]=(const float4*)(ems+(nt*8+k)*EMP);
        float a[32];
#pragma unroll
        for(int i=0;i<32;i++) a[i]=0.f;
        for(int r=0;r<EMP/4;r++){
            float4 ev[8];
#pragma unroll
            for(int k=0;k<8;k++) ev[k]=ep[k][r];
#pragma unroll
            for(int i=0;i<4;i++){
                float4 xv=xp[i][r];
#pragma unroll
                for(int k=0;k<8;k++)
                    a[i*8+k]+=xv.x*ev[k].x+xv.y*ev[k].y+xv.z*ev[k].z+xv.w*ev[k].w;
            }
        }
#pragma unroll
        for(int i=0;i<4;i++){
            int b=bt*4+i;
            float s1v=s1s[b];
#pragma unroll
            for(int kq=0;kq<2;kq++){
                float4 o;
                o.x=-0.5f*(s2s[nt*8+kq*4+0]-2.f*a[i*8+kq*4+0]+s1v);
                o.y=-0.5f*(s2s[nt*8+kq*4+1]-2.f*a[i*8+kq*4+1]+s1v);
                o.z=-0.5f*(s2s[nt*8+kq*4+2]-2.f*a[i*8+kq*4+2]+s1v);
                o.w=-0.5f*(s2s[nt*8+kq*4+3]-2.f*a[i*8+kq*4+3]+s1v);
                *(float4*)(obs+(size_t)b*NN+n0+nt*8+kq*4)=o;
            }
        }
    }
}

// ------------------- launch (7 kernels) -------------------
extern "C" void kernel_launch(void* const* d_in,const int* in_sizes,int n_in,
                              void* d_out,int out_size){
    const float* x     =(const float*)d_in[0];
    const float* conv_w=(const float*)d_in[1];
    const float* conv_b=(const float*)d_in[2];
    const float* ebn2_g=(const float*)d_in[3];
    const float* ebn2_b=(const float*)d_in[4];
    const float* fc1_w =(const float*)d_in[5];
    const float* fc1_b =(const float*)d_in[6];
    const float* ebn1_g=(const float*)d_in[7];
    const float* ebn1_b=(const float*)d_in[8];
    const float* fc2_w =(const float*)d_in[9];
    const float* fc2_b =(const float*)d_in[10];
    const float* embeds=(const float*)d_in[11];
    const float* dfc1_w=(const float*)d_in[12];
    const float* dfc1_b=(const float*)d_in[13];
    const float* dbn1_g=(const float*)d_in[14];
    const float* dbn1_b=(const float*)d_in[15];
    const float* dbn1_rm=(const float*)d_in[16];
    const float* dbn1_rv=(const float*)d_in[17];
    const float* dfc2_w=(const float*)d_in[18];
    const float* dfc2_b=(const float*)d_in[19];
    const float* dbn2_g=(const float*)d_in[20];
    const float* dbn2_b=(const float*)d_in[21];
    const float* dbn2_rm=(const float*)d_in[22];
    const float* dbn2_rv=(const float*)d_in[23];
    const float* dct1_w=(const float*)d_in[24];
    const float* dct1_b=(const float*)d_in[25];
    const float* dbn3_g=(const float*)d_in[26];
    const float* dbn3_b=(const float*)d_in[27];
    const float* dbn3_rm=(const float*)d_in[28];
    const float* dbn3_rv=(const float*)d_in[29];
    const float* dct2_w=(const float*)d_in[30];
    const float* dct2_b=(const float*)d_in[31];

    float* out=(float*)d_out;
    float* obs=out;
    float* dist=out+(size_t)Bb*NN;
    float* loss=dist+(size_t)Bb*LL;

    cudaFuncSetAttribute(k_gemm1,cudaFuncAttributeMaxDynamicSharedMemorySize,G1_SME);
    cudaFuncSetAttribute(k_gemm2,cudaFuncAttributeMaxDynamicSharedMemorySize,G2_SME);
    cudaFuncSetAttribute(k_obs,cudaFuncAttributeMaxDynamicSharedMemorySize,OBS_SMEM);

    k_prep<<<256,256>>>(x,embeds,dfc1_w,dfc1_b,dbn1_g,dbn1_b,dbn1_rm,dbn1_rv,
                        dfc2_w,dfc2_b,dbn2_g,dbn2_b,dbn2_rm,dbn2_rv,
                        dct1_w,dct1_b,dbn3_g,dbn3_b,dbn3_rm,dbn3_rv);
    k_gemm1<<<729,256,G1_SME>>>();
    k_gemm2<<<dim3(365,2),256,G2_SME>>>(dct2_w,dct2_b);
    k_enc1<<<64,256>>>(x,conv_w,conv_b,ebn2_g,ebn2_b);
    k_enc2<<<256,256>>>(fc1_w,fc1_b,ebn1_g,ebn1_b);
    k_enc_head<<<Bb,128>>>(fc2_w,fc2_b,dist,loss);
    k_obs<<<NN/ONB,256,OBS_SMEM>>>(x,obs);
}

// round 14
// speedup vs baseline: 5.2220x; 1.0347x over previous
#include <cuda_runtime.h>
#include <cuda_bf16.h>
#include <math.h>
#include <stdint.h>

#define EPSV 1e-5f
constexpr int Bb=64, NN=46656, F0=147, E1=1024, LL=36, H1=1024, H2=256, EMP=148;
constexpr int NPAD=46720;   // 365*128

__device__ float g_T[36*H1];
__device__ float g_T2[108*H1];          // pair tables, b1 folded into p=0
__device__ float g_b1[H1];
__device__ float g_b2f[H2];
__device__ float g_b3f[16];
__device__ float g_s1[Bb];
__device__ float g_e0[Bb*256];
__device__ float g_e1[Bb*E1];
__device__ __nv_bfloat16 g_W2nh[H2*H1];   // [o][j], bn2-scaled hi
__device__ __nv_bfloat16 g_W2nl[H2*H1];
__device__ __nv_bfloat16 g_W1nh[784*H2];  // [p'=hw*16+ch][i], bn3-scaled hi
__device__ __nv_bfloat16 g_W1nl[784*H2];
__device__ __nv_bfloat16 g_A2h[(size_t)NPAD*288];  // padded MMA layout: [row][kc*72+off]
__device__ __nv_bfloat16 g_A2l[(size_t)NPAD*288];
__device__ float g_em[(size_t)NPAD*EMP];  // col 147 stays 0

__device__ __forceinline__ void bsplit(float v,__nv_bfloat16&hi,__nv_bfloat16&lo){
    hi=__float2bfloat16(v); lo=__float2bfloat16(v-__bfloat162float(hi));
}
__device__ __forceinline__ void mma16816(float* c,const uint32_t* a,uint32_t b0,uint32_t b1){
    asm volatile("mma.sync.aligned.m16n8k16.row.col.f32.bf16.bf16.f32 "
        "{%0,%1,%2,%3},{%4,%5,%6,%7},{%8,%9},{%0,%1,%2,%3};"
        :"+f"(c[0]),"+f"(c[1]),"+f"(c[2]),"+f"(c[3])
        :"r"(a[0]),"r"(a[1]),"r"(a[2]),"r"(a[3]),"r"(b0),"r"(b1));
}
__device__ __forceinline__ uint32_t pack2(float va,float vb){
    uint32_t hp; asm("cvt.rn.bf16x2.f32 %0,%1,%2;":"=r"(hp):"f"(vb),"f"(va)); return hp;
}
__device__ __forceinline__ void cp16(void* dst,const void* src){
    uint32_t d; asm("{ .reg .u64 t; cvta.to.shared.u64 t, %1; cvt.u32.u64 %0, t; }":"=r"(d):"l"(dst));
    asm volatile("cp.async.cg.shared.global [%0], [%1], 16;"::"r"(d),"l"(src):"memory");
}
#define CP_COMMIT() asm volatile("cp.async.commit_group;":::"memory")
#define CP_WAIT0()  asm volatile("cp.async.wait_group 0;":::"memory")

// ------------------- k_prep: tables + misc (round-11 exact) -------------------
__global__ void k_prep(
    const float* __restrict__ x,
    const float* __restrict__ embeds,const float* __restrict__ dfc1_w,
    const float* __restrict__ dfc1_b,const float* __restrict__ g1,const float* __restrict__ be1,
    const float* __restrict__ rm1,const float* __restrict__ rv1,
    const float* __restrict__ dfc2_w,const float* __restrict__ dfc2_b,
    const float* __restrict__ g2,const float* __restrict__ be2,
    const float* __restrict__ rm2,const float* __restrict__ rv2,
    const float* __restrict__ dct1_w,const float* __restrict__ dct1_b,
    const float* __restrict__ g3,const float* __restrict__ be3,
    const float* __restrict__ rm3,const float* __restrict__ rv3){
    int stride=gridDim.x*blockDim.x, tid=blockIdx.x*blockDim.x+threadIdx.x;
    for(int i=tid;i<36*H1;i+=stride){
        int m=i>>10, j=i&1023, v=m/6;
        const float* e=embeds+m*32;
        const float* w=dfc1_w+(size_t)j*192+v*32;
        float s=0.f;
#pragma unroll
        for(int d=0;d<32;d++) s+=e[d]*w[d];
        g_T[i]=g1[j]*rsqrtf(rv1[j]+EPSV)*s;
    }
    for(int j=tid;j<H1;j+=stride){
        float a=g1[j]*rsqrtf(rv1[j]+EPSV);
        g_b1[j]=a*(dfc1_b[j]-rm1[j])+be1[j];
    }
    for(int i=tid;i<H2*H1;i+=stride){
        int o=i>>10;
        float a=g2[o]*rsqrtf(rv2[o]+EPSV);
        __nv_bfloat16 hi,lo; bsplit(a*dfc2_w[i],hi,lo);
        g_W2nh[i]=hi; g_W2nl[i]=lo;
    }
    for(int o=tid;o<H2;o+=stride){
        float a=g2[o]*rsqrtf(rv2[o]+EPSV);
        g_b2f[o]=a*(dfc2_b[o]-rm2[o])+be2[o];
    }
    for(int e=tid;e<784*H2;e+=stride){
        int pcol=e>>8, i=e&255, hw=pcol>>4, ch=pcol&15;
        float a=g3[ch]*rsqrtf(rv3[ch]+EPSV);
        __nv_bfloat16 hi,lo; bsplit(a*dct1_w[i*784+ch*49+hw],hi,lo);
        g_W1nh[e]=hi; g_W1nl[e]=lo;
    }
    for(int o=tid;o<16;o+=stride){
        float a=g3[o]*rsqrtf(rv3[o]+EPSV);
        g_b3f[o]=a*(dct1_b[o]-rm3[o])+be3[o];
    }
    for(int b=tid;b<Bb;b+=stride){
        float s=0.f;
        for(int r=0;r<F0;r++){float v=x[b*F0+r];s+=v*v;}
        g_s1[b]=s;
    }
}
__global__ void k_prep_pairs(){
    int m=blockIdx.x;            // 0..107
    int p=m/36, ab=m%36, a=ab/6, b=ab%6;
    const float* ta=g_T+(p*12+a)*H1;
    const float* tbp=g_T+(p*12+6+b)*H1;
    float* dst=g_T2+(size_t)m*H1;
    for(int j=threadIdx.x;j<H1;j+=blockDim.x){
        float s=ta[j]+tbp[j];
        if(p==0) s+=g_b1[j];
        dst[j]=s;
    }
}

// ------------------- encoder (round-11 exact) -------------------
__global__ void k_enc1(const float* __restrict__ x,const float* __restrict__ w,
                       const float* __restrict__ bias,
                       const float* __restrict__ gg,const float* __restrict__ bb){
    int t=threadIdx.x, jl=t>>6, b=t&63, j=blockIdx.x*4+jl;
    const float* wj=w+(size_t)j*F0;
    const float* xb=x+(size_t)b*F0;
    float s=bias[j];
    for(int r=0;r<F0;r++) s+=xb[r]*__ldg(wj+r);
    __shared__ float red[4][2];
    int wh=(t>>5)&1;
    float p=s;
    for(int o=16;o;o>>=1) p+=__shfl_xor_sync(0xffffffffu,p,o);
    if((t&31)==0) red[jl][wh]=p;
    __syncthreads();
    float m=(red[jl][0]+red[jl][1])*(1.f/64.f);
    __syncthreads();
    float d=s-m; p=d*d;
    for(int o=16;o;o>>=1) p+=__shfl_xor_sync(0xffffffffu,p,o);
    if((t&31)==0) red[jl][wh]=p;
    __syncthreads();
    float var=(red[jl][0]+red[jl][1])*(1.f/64.f);
    g_e0[b*256+j]=fmaxf(gg[j]*d*rsqrtf(var+EPSV)+bb[j],0.f);
}
__global__ void k_enc2(const float* __restrict__ w,const float* __restrict__ bias,
                       const float* __restrict__ gg,const float* __restrict__ bb){
    int t=threadIdx.x, jl=t>>6, b=t&63, j=blockIdx.x*4+jl;
    const float4* wj=(const float4*)(w+(size_t)j*256);
    const float4* xb=(const float4*)(g_e0+b*256);
    float s=bias[j];
#pragma unroll 8
    for(int r=0;r<64;r++){
        float4 a=xb[r], c=__ldg(wj+r);
        s+=a.x*c.x+a.y*c.y+a.z*c.z+a.w*c.w;
    }
    __shared__ float red[4][2];
    int wh=(t>>5)&1;
    float p=s;
    for(int o=16;o;o>>=1) p+=__shfl_xor_sync(0xffffffffu,p,o);
    if((t&31)==0) red[jl][wh]=p;
    __syncthreads();
    float m=(red[jl][0]+red[jl][1])*(1.f/64.f);
    __syncthreads();
    float d=s-m; p=d*d;
    for(int o=16;o;o>>=1) p+=__shfl_xor_sync(0xffffffffu,p,o);
    if((t&31)==0) red[jl][wh]=p;
    __syncthreads();
    float var=(red[jl][0]+red[jl][1])*(1.f/64.f);
    g_e1[(size_t)b*E1+j]=fmaxf(gg[j]*d*rsqrtf(var+EPSV)+bb[j],0.f);
}
__global__ void k_enc_head(const float* __restrict__ fc2_w,const float* __restrict__ fc2_b,
                           float* __restrict__ dist_out,float* __restrict__ loss_out){
    int b=blockIdx.x;
    __shared__ float es[E1];
    __shared__ float lg[LL];
    for(int j=threadIdx.x;j<E1;j+=blockDim.x) es[j]=g_e1[(size_t)b*E1+j];
    __syncthreads();
    if(threadIdx.x<LL){
        const float* w=fc2_w+(size_t)threadIdx.x*E1;
        float s=fc2_b[threadIdx.x];
        for(int j=0;j<E1;j++) s+=es[j]*__ldg(w+j);
        lg[threadIdx.x]=s;
    }
    __syncthreads();
    if(threadIdx.x==0){
        float loss=0.f;
        for(int v=0;v<6;v++){
            float mx=-1e30f;
            for(int k=0;k<6;k++) mx=fmaxf(mx,lg[v*6+k]);
            float ex[6],se=0.f;
            for(int k=0;k<6;k++){ex[k]=expf(lg[v*6+k]-mx);se+=ex[k];}
            float inv=1.f/se;
            for(int k=0;k<6;k++){
                float pp=ex[k]*inv;
                dist_out[b*LL+v*6+k]=pp;
                loss+=pp*logf(pp+1e-10f);
            }
        }
        loss_out[b]=0.1f*loss;
    }
}

// ------------------- GEMM1: round-8/11 exact -------------------
constexpr int G1_T=0, G1_AH=1024, G1_AL=G1_AH+9216, G1_BH=G1_AL+9216, G1_BL=G1_BH+36864;
constexpr int G1_SME=G1_BL+36864;   // 93184 B
__global__ void __launch_bounds__(256,2) k_gemm1(){
    extern __shared__ char sm[];
    int* tb=(int*)(sm+G1_T);
    const int t=threadIdx.x, wid=t>>5, lane=t&31, gid=lane>>2, tig=lane&3;
    const int n0=blockIdx.x*64;
    if(t<192){
        int r=t/3, c=t-r*3, n=n0+r;
        int val=(c==0)? (n/1296)%36 : (c==1)? 36+(n/36)%36 : 72+n%36;
        tb[t]=val*H1;
    }
    float acc[64];
#pragma unroll
    for(int i=0;i<64;i++) acc[i]=0.f;
    const int mrow0=(wid&3)*16, ncol0=(wid>>2)*128;

    for(int kc=0;kc<16;kc++){
        __syncthreads();
        const int kb=kc*64;
#pragma unroll
        for(int i=0;i<8;i++){
            int u=i*256+t, row=u>>3, part=u&7;
            cp16(sm+G1_BH+row*144+part*16,(const char*)g_W2nh+(size_t)row*2048+kb*2+part*16);
            cp16(sm+G1_BL+row*144+part*16,(const char*)g_W2nl+(size_t)row*2048+kb*2+part*16);
        }
        CP_COMMIT();
#pragma unroll
        for(int i=0;i<8;i++){
            int e=i*256+t, r=e>>5, l2=(e&31)*2, j=kb+l2;
            const int* tr=tb+r*3;
            float2 s0=*(const float2*)(g_T2+tr[0]+j);
            float2 s1=*(const float2*)(g_T2+tr[1]+j);
            float2 s2=*(const float2*)(g_T2+tr[2]+j);
            float va=fmaxf(s0.x+s1.x+s2.x,0.f), vb=fmaxf(s0.y+s1.y+s2.y,0.f);
            uint32_t hp=pack2(va,vb);
            float la=va-__uint_as_float(hp<<16), lb=vb-__uint_as_float(hp&0xffff0000u);
            uint32_t lp=pack2(la,lb);
            *(uint32_t*)(sm+G1_AH+r*144+l2*2)=hp;
            *(uint32_t*)(sm+G1_AL+r*144+l2*2)=lp;
        }
        CP_WAIT0();
        __syncthreads();
#pragma unroll
        for(int ks=0;ks<4;ks++){
            int ao=(mrow0+gid)*144+ks*32+tig*4;
            uint32_t ah[4],al[4];
            ah[0]=*(const uint32_t*)(sm+G1_AH+ao);
            ah[1]=*(const uint32_t*)(sm+G1_AH+ao+1152);
            ah[2]=*(const uint32_t*)(sm+G1_AH+ao+16);
            ah[3]=*(const uint32_t*)(sm+G1_AH+ao+1168);
            al[0]=*(const uint32_t*)(sm+G1_AL+ao);
            al[1]=*(const uint32_t*)(sm+G1_AL+ao+1152);
            al[2]=*(const uint32_t*)(sm+G1_AL+ao+16);
            al[3]=*(const uint32_t*)(sm+G1_AL+ao+1168);
#pragma unroll
            for(int g=0;g<16;g++){
                int bo=(ncol0+g*8+gid)*144+ks*32+tig*4;
                uint32_t bh0=*(const uint32_t*)(sm+G1_BH+bo);
                uint32_t bh1=*(const uint32_t*)(sm+G1_BH+bo+16);
                uint32_t bl0=*(const uint32_t*)(sm+G1_BL+bo);
                uint32_t bl1=*(const uint32_t*)(sm+G1_BL+bo+16);
                float* c=acc+g*4;
                mma16816(c,ah,bh0,bh1);
                mma16816(c,ah,bl0,bl1);
                mma16816(c,al,bh0,bh1);
            }
        }
    }
    const int r0=n0+mrow0+gid;
#pragma unroll
    for(int nt=0;nt<16;nt++){
        int col=ncol0+nt*8+tig*2;
        float ba=g_b2f[col], bb2=g_b2f[col+1];
        size_t base=(size_t)(col>>6)*144+(col&63)*2;
        float v00=fmaxf(acc[nt*4+0]+ba,0.f), v01=fmaxf(acc[nt*4+1]+bb2,0.f);
        float v10=fmaxf(acc[nt*4+2]+ba,0.f), v11=fmaxf(acc[nt*4+3]+bb2,0.f);
        uint32_t hp=pack2(v00,v01);
        float la=v00-__uint_as_float(hp<<16), lb=v01-__uint_as_float(hp&0xffff0000u);
        *(uint32_t*)((char*)g_A2h+(size_t)r0*576+base)=hp;
        *(uint32_t*)((char*)g_A2l+(size_t)r0*576+base)=pack2(la,lb);
        hp=pack2(v10,v11);
        la=v10-__uint_as_float(hp<<16); lb=v11-__uint_as_float(hp&0xffff0000u);
        *(uint32_t*)((char*)g_A2h+(size_t)(r0+8)*576+base)=hp;
        *(uint32_t*)((char*)g_A2l+(size_t)(r0+8)*576+base)=pack2(la,lb);
    }
}

// ------------------- GEMM2: round-8/11 exact (grid (365,2)) -------------------
constexpr int G2_BH0=0, G2_BL0=16128, G2_BH1=32256, G2_BL1=48384;
constexpr int G2_SME=64512;
__global__ void __launch_bounds__(256,2)
k_gemm2(const float* __restrict__ dct2_w,const float* __restrict__ dct2_b){
    extern __shared__ char sm[];
    const int t=threadIdx.x, wid=t>>5, lane=t&31, gid=lane>>2, tig=lane&3;
    const int n0=blockIdx.x*128;
    const int s0=blockIdx.y, scnt=blockIdx.y? 3:4;
    float wv[12], b3v[4], dbv[3];
    {
        int ch0=tig*2;
        int chs[4]={ch0,ch0+1,8+ch0,9+ch0};
#pragma unroll
        for(int q=0;q<4;q++){
            b3v[q]=g_b3f[chs[q]];
#pragma unroll
            for(int o=0;o<3;o++) wv[q*3+o]=dct2_w[chs[q]*3+o];
        }
#pragma unroll
        for(int o=0;o<3;o++) dbv[o]=dct2_b[o];
    }
    const int row0=n0+wid*16+gid, row1=row0+8;
    const char* A2h=(const char*)g_A2h;
    const char* A2l=(const char*)g_A2l;

#define G2_STAGE(S,KC,BUF) do{ \
    int _bh=(BUF)? G2_BH1:G2_BH0, _bl=(BUF)? G2_BL1:G2_BL0; \
    _Pragma("unroll") \
    for(int _i=0;_i<7;_i++){ \
        int _u=_i*256+t; int _kind=_u>=896; int _uu=_kind? _u-896:_u; int _row=_uu>>3,_part=_uu&7; \
        const char* _src=(_kind? (const char*)g_W1nl:(const char*)g_W1nh)+(size_t)((S)*112+_row)*512+(KC)*128+_part*16; \
        cp16(sm+(_kind? _bl:_bh)+_row*144+_part*16,_src); \
    } CP_COMMIT(); }while(0)

    G2_STAGE(s0,0,0);
    CP_WAIT0();
    __syncthreads();
    int cc=0;
    for(int si=0;si<scnt;si++){
        int s=s0+si*2;
        float acc[56];
#pragma unroll
        for(int i=0;i<56;i++) acc[i]=0.f;
        for(int kc=0;kc<4;kc++){
            int buf=cc&1;
            if(cc+1<scnt*4){
                int nn=cc+1, s2=s0+(nn>>2)*2, kc2=nn&3;
                G2_STAGE(s2,kc2,buf^1);
            }
            int bh=buf? G2_BH1:G2_BH0, bl=buf? G2_BL1:G2_BL0;
#pragma unroll
            for(int ks=0;ks<4;ks++){
                size_t ao=(size_t)kc*144+(size_t)(ks*32+tig*4);
                uint32_t ah[4],al[4];
                ah[0]=*(const uint32_t*)(A2h+(size_t)row0*576+ao);
                ah[1]=*(const uint32_t*)(A2h+(size_t)row1*576+ao);
                ah[2]=*(const uint32_t*)(A2h+(size_t)row0*576+ao+16);
                ah[3]=*(const uint32_t*)(A2h+(size_t)row1*576+ao+16);
                al[0]=*(const uint32_t*)(A2l+(size_t)row0*576+ao);
                al[1]=*(const uint32_t*)(A2l+(size_t)row1*576+ao);
                al[2]=*(const uint32_t*)(A2l+(size_t)row0*576+ao+16);
                al[3]=*(const uint32_t*)(A2l+(size_t)row1*576+ao+16);
#pragma unroll
                for(int g=0;g<14;g++){
                    int bo=(g*8+gid)*144+ks*32+tig*4;
                    uint32_t bh0=*(const uint32_t*)(sm+bh+bo);
                    uint32_t bh1=*(const uint32_t*)(sm+bh+bo+16);
                    uint32_t bl0=*(const uint32_t*)(sm+bl+bo);
                    uint32_t bl1=*(const uint32_t*)(sm+bl+bo+16);
                    float* c=acc+g*4;
                    mma16816(c,ah,bh0,bh1);
                    mma16816(c,ah,bl0,bl1);
                    mma16816(c,al,bh0,bh1);
                }
            }
            CP_WAIT0();
            __syncthreads();
            cc++;
        }
#pragma unroll
        for(int hw=0;hw<7;hw++){
            float hA0=fmaxf(acc[hw*8+0]+b3v[0],0.f);
            float hA1=fmaxf(acc[hw*8+1]+b3v[1],0.f);
            float hB0=fmaxf(acc[hw*8+4]+b3v[2],0.f);
            float hB1=fmaxf(acc[hw*8+5]+b3v[3],0.f);
            float hC0=fmaxf(acc[hw*8+2]+b3v[0],0.f);
            float hC1=fmaxf(acc[hw*8+3]+b3v[1],0.f);
            float hD0=fmaxf(acc[hw*8+6]+b3v[2],0.f);
            float hD1=fmaxf(acc[hw*8+7]+b3v[3],0.f);
            float p[6];
#pragma unroll
            for(int o=0;o<3;o++){
                p[o]  =hA0*wv[o]+hA1*wv[3+o]+hB0*wv[6+o]+hB1*wv[9+o];
                p[3+o]=hC0*wv[o]+hC1*wv[3+o]+hD0*wv[6+o]+hD1*wv[9+o];
            }
#pragma unroll
            for(int off=1;off<4;off<<=1)
#pragma unroll
                for(int q=0;q<6;q++) p[q]+=__shfl_xor_sync(0xffffffffu,p[q],off);
            if(tig<3){
                g_em[(size_t)row0*EMP+tig*49+s*7+hw]=p[tig]+dbv[tig];
                g_em[(size_t)row1*EMP+tig*49+s*7+hw]=p[3+tig]+dbv[tig];
            }
        }
    }
#undef G2_STAGE
}

// ------------------- obs: ONB=96, occ 2, 4x8 register tiles -------------------
constexpr int ONB=96;
constexpr int OBS_SMEM=(ONB*EMP+64*EMP+ONB+64)*4;
__global__ void __launch_bounds__(256,2)
k_obs(const float* __restrict__ x,float* __restrict__ obs){
    extern __shared__ float smf[];
    float* ems=smf;
    float* xs=ems+ONB*EMP;
    float* s2s=xs+64*EMP;
    float* s1s=s2s+ONB;
    const int t=threadIdx.x, n0=blockIdx.x*ONB;
    {
        float4* dst=(float4*)ems;
        const float4* src=(const float4*)(g_em+(size_t)n0*EMP);
        for(int id=t;id<ONB*(EMP/4);id+=256) dst[id]=__ldg(src+id);
    }
    for(int id=t;id<64*F0;id+=256){
        int r=id/F0, c=id-r*F0;
        xs[r*EMP+c]=x[id];
    }
    if(t<64){ xs[t*EMP+F0]=0.f; s1s[t]=g_s1[t]; }
    __syncthreads();
    if(t<ONB){
        const float4* e=(const float4*)(ems+t*EMP);
        float s=0.f;
#pragma unroll 4
        for(int r=0;r<EMP/4;r++){
            float4 v=e[r];
            s+=v.x*v.x+v.y*v.y+v.z*v.z+v.w*v.w;
        }
        s2s[t]=s;
    }
    __syncthreads();
    if(t<192){
        int bt=t/12, nt=t%12;      // 16 b-groups x 12 n-groups; tile 4b x 8n
        const float4* xp[4];
        const float4* ep[8];
#pragma unroll
        for(int i=0;i<4;i++) xp[i]=(const float4*)(xs+(bt*4+i)*EMP);
#pragma unroll
        for(int k=0;k<8;k++) ep[k]=(const float4*)(ems+(nt*8+k)*EMP);
        float a[32];
#pragma unroll
        for(int i=0;i<32;i++) a[i]=0.f;
        for(int r=0;r<EMP/4;r++){
            float4 ev[8];
#pragma unroll
            for(int k=0;k<8;k++) ev[k]=ep[k][r];
#pragma unroll
            for(int i=0;i<4;i++){
                float4 xv=xp[i][r];
#pragma unroll
                for(int k=0;k<8;k++)
                    a[i*8+k]+=xv.x*ev[k].x+xv.y*ev[k].y+xv.z*ev[k].z+xv.w*ev[k].w;
            }
        }
#pragma unroll
        for(int i=0;i<4;i++){
            int b=bt*4+i;
            float s1v=s1s[b];
#pragma unroll
            for(int kq=0;kq<2;kq++){
                float4 o;
                o.x=-0.5f*(s2s[nt*8+kq*4+0]-2.f*a[i*8+kq*4+0]+s1v);
                o.y=-0.5f*(s2s[nt*8+kq*4+1]-2.f*a[i*8+kq*4+1]+s1v);
                o.z=-0.5f*(s2s[nt*8+kq*4+2]-2.f*a[i*8+kq*4+2]+s1v);
                o.w=-0.5f*(s2s[nt*8+kq*4+3]-2.f*a[i*8+kq*4+3]+s1v);
                *(float4*)(obs+(size_t)b*NN+n0+nt*8+kq*4)=o;
            }
        }
    }
}

// ------------------- launch (8 kernels, round-11 order) -------------------
extern "C" void kernel_launch(void* const* d_in,const int* in_sizes,int n_in,
                              void* d_out,int out_size){
    const float* x     =(const float*)d_in[0];
    const float* conv_w=(const float*)d_in[1];
    const float* conv_b=(const float*)d_in[2];
    const float* ebn2_g=(const float*)d_in[3];
    const float* ebn2_b=(const float*)d_in[4];
    const float* fc1_w =(const float*)d_in[5];
    const float* fc1_b =(const float*)d_in[6];
    const float* ebn1_g=(const float*)d_in[7];
    const float* ebn1_b=(const float*)d_in[8];
    const float* fc2_w =(const float*)d_in[9];
    const float* fc2_b =(const float*)d_in[10];
    const float* embeds=(const float*)d_in[11];
    const float* dfc1_w=(const float*)d_in[12];
    const float* dfc1_b=(const float*)d_in[13];
    const float* dbn1_g=(const float*)d_in[14];
    const float* dbn1_b=(const float*)d_in[15];
    const float* dbn1_rm=(const float*)d_in[16];
    const float* dbn1_rv=(const float*)d_in[17];
    const float* dfc2_w=(const float*)d_in[18];
    const float* dfc2_b=(const float*)d_in[19];
    const float* dbn2_g=(const float*)d_in[20];
    const float* dbn2_b=(const float*)d_in[21];
    const float* dbn2_rm=(const float*)d_in[22];
    const float* dbn2_rv=(const float*)d_in[23];
    const float* dct1_w=(const float*)d_in[24];
    const float* dct1_b=(const float*)d_in[25];
    const float* dbn3_g=(const float*)d_in[26];
    const float* dbn3_b=(const float*)d_in[27];
    const float* dbn3_rm=(const float*)d_in[28];
    const float* dbn3_rv=(const float*)d_in[29];
    const float* dct2_w=(const float*)d_in[30];
    const float* dct2_b=(const float*)d_in[31];

    float* out=(float*)d_out;
    float* obs=out;
    float* dist=out+(size_t)Bb*NN;
    float* loss=dist+(size_t)Bb*LL;

    cudaFuncSetAttribute(k_gemm1,cudaFuncAttributeMaxDynamicSharedMemorySize,G1_SME);
    cudaFuncSetAttribute(k_gemm2,cudaFuncAttributeMaxDynamicSharedMemorySize,G2_SME);
    cudaFuncSetAttribute(k_obs,cudaFuncAttributeMaxDynamicSharedMemorySize,OBS_SMEM);

    k_prep<<<256,256>>>(x,embeds,dfc1_w,dfc1_b,dbn1_g,dbn1_b,dbn1_rm,dbn1_rv,
                        dfc2_w,dfc2_b,dbn2_g,dbn2_b,dbn2_rm,dbn2_rv,
                        dct1_w,dct1_b,dbn3_g,dbn3_b,dbn3_rm,dbn3_rv);
    k_prep_pairs<<<108,256>>>();
    k_gemm1<<<729,256,G1_SME>>>();
    k_gemm2<<<dim3(365,2),256,G2_SME>>>(dct2_w,dct2_b);
    k_enc1<<<64,256>>>(x,conv_w,conv_b,ebn2_g,ebn2_b);
    k_enc2<<<256,256>>>(fc1_w,fc1_b,ebn1_g,ebn1_b);
    k_enc_head<<<Bb,128>>>(fc2_w,fc2_b,dist,loss);
    k_obs<<<NN/ONB,256,OBS_SMEM>>>(x,obs);
}

// round 15
// speedup vs baseline: 5.6357x; 1.0792x over previous
#include <cuda_runtime.h>
#include <cuda_bf16.h>
#include <math.h>
#include <stdint.h>

#define EPSV 1e-5f
constexpr int Bb=64, NN=46656, F0=147, E1=1024, LL=36, H1=1024, H2=256, EMP=148;
constexpr int NPAD=46720;   // 365*128

__device__ float g_T[36*H1];
__device__ float g_T2[108*H1];          // pair tables, b1 folded into p=0
__device__ float g_b1[H1];
__device__ float g_b2f[H2];
__device__ float g_b3f[16];
__device__ float g_s1[Bb];
__device__ float g_e0[Bb*256];
__device__ float g_e1[Bb*E1];
__device__ __nv_bfloat16 g_W2nh[H2*H1];   // [o][j], bn2-scaled hi
__device__ __nv_bfloat16 g_W2nl[H2*H1];
__device__ __nv_bfloat16 g_W1nh[784*H2];  // [p'=hw*16+ch][i], bn3-scaled hi
__device__ __nv_bfloat16 g_W1nl[784*H2];
// thread-major MMA layout: row*512B + kc*128 + tig*32 + ks*8 + half*4
__device__ __nv_bfloat16 g_A2h[(size_t)NPAD*256];
__device__ __nv_bfloat16 g_A2l[(size_t)NPAD*256];
__device__ float g_em[(size_t)NPAD*EMP];  // col 147 stays 0

__device__ __forceinline__ void bsplit(float v,__nv_bfloat16&hi,__nv_bfloat16&lo){
    hi=__float2bfloat16(v); lo=__float2bfloat16(v-__bfloat162float(hi));
}
__device__ __forceinline__ void mma16816(float* c,const uint32_t* a,uint32_t b0,uint32_t b1){
    asm volatile("mma.sync.aligned.m16n8k16.row.col.f32.bf16.bf16.f32 "
        "{%0,%1,%2,%3},{%4,%5,%6,%7},{%8,%9},{%0,%1,%2,%3};"
        :"+f"(c[0]),"+f"(c[1]),"+f"(c[2]),"+f"(c[3])
        :"r"(a[0]),"r"(a[1]),"r"(a[2]),"r"(a[3]),"r"(b0),"r"(b1));
}
__device__ __forceinline__ uint32_t pack2(float va,float vb){
    uint32_t hp; asm("cvt.rn.bf16x2.f32 %0,%1,%2;":"=r"(hp):"f"(vb),"f"(va)); return hp;
}
__device__ __forceinline__ void cp16(void* dst,const void* src){
    uint32_t d; asm("{ .reg .u64 t; cvta.to.shared.u64 t, %1; cvt.u32.u64 %0, t; }":"=r"(d):"l"(dst));
    asm volatile("cp.async.cg.shared.global [%0], [%1], 16;"::"r"(d),"l"(src):"memory");
}
#define CP_COMMIT() asm volatile("cp.async.commit_group;":::"memory")
#define CP_WAIT0()  asm volatile("cp.async.wait_group 0;":::"memory")

// ------------------- k_prep + pairs (round-11 exact) -------------------
__global__ void k_prep(
    const float* __restrict__ x,
    const float* __restrict__ embeds,const float* __restrict__ dfc1_w,
    const float* __restrict__ dfc1_b,const float* __restrict__ g1,const float* __restrict__ be1,
    const float* __restrict__ rm1,const float* __restrict__ rv1,
    const float* __restrict__ dfc2_w,const float* __restrict__ dfc2_b,
    const float* __restrict__ g2,const float* __restrict__ be2,
    const float* __restrict__ rm2,const float* __restrict__ rv2,
    const float* __restrict__ dct1_w,const float* __restrict__ dct1_b,
    const float* __restrict__ g3,const float* __restrict__ be3,
    const float* __restrict__ rm3,const float* __restrict__ rv3){
    int stride=gridDim.x*blockDim.x, tid=blockIdx.x*blockDim.x+threadIdx.x;
    for(int i=tid;i<36*H1;i+=stride){
        int m=i>>10, j=i&1023, v=m/6;
        const float* e=embeds+m*32;
        const float* w=dfc1_w+(size_t)j*192+v*32;
        float s=0.f;
#pragma unroll
        for(int d=0;d<32;d++) s+=e[d]*w[d];
        g_T[i]=g1[j]*rsqrtf(rv1[j]+EPSV)*s;
    }
    for(int j=tid;j<H1;j+=stride){
        float a=g1[j]*rsqrtf(rv1[j]+EPSV);
        g_b1[j]=a*(dfc1_b[j]-rm1[j])+be1[j];
    }
    for(int i=tid;i<H2*H1;i+=stride){
        int o=i>>10;
        float a=g2[o]*rsqrtf(rv2[o]+EPSV);
        __nv_bfloat16 hi,lo; bsplit(a*dfc2_w[i],hi,lo);
        g_W2nh[i]=hi; g_W2nl[i]=lo;
    }
    for(int o=tid;o<H2;o+=stride){
        float a=g2[o]*rsqrtf(rv2[o]+EPSV);
        g_b2f[o]=a*(dfc2_b[o]-rm2[o])+be2[o];
    }
    for(int e=tid;e<784*H2;e+=stride){
        int pcol=e>>8, i=e&255, hw=pcol>>4, ch=pcol&15;
        float a=g3[ch]*rsqrtf(rv3[ch]+EPSV);
        __nv_bfloat16 hi,lo; bsplit(a*dct1_w[i*784+ch*49+hw],hi,lo);
        g_W1nh[e]=hi; g_W1nl[e]=lo;
    }
    for(int o=tid;o<16;o+=stride){
        float a=g3[o]*rsqrtf(rv3[o]+EPSV);
        g_b3f[o]=a*(dct1_b[o]-rm3[o])+be3[o];
    }
    for(int b=tid;b<Bb;b+=stride){
        float s=0.f;
        for(int r=0;r<F0;r++){float v=x[b*F0+r];s+=v*v;}
        g_s1[b]=s;
    }
}
__global__ void k_prep_pairs(){
    int m=blockIdx.x;
    int p=m/36, ab=m%36, a=ab/6, b=ab%6;
    const float* ta=g_T+(p*12+a)*H1;
    const float* tbp=g_T+(p*12+6+b)*H1;
    float* dst=g_T2+(size_t)m*H1;
    for(int j=threadIdx.x;j<H1;j+=blockDim.x){
        float s=ta[j]+tbp[j];
        if(p==0) s+=g_b1[j];
        dst[j]=s;
    }
}

// ------------------- encoder (round-11 exact) -------------------
__global__ void k_enc1(const float* __restrict__ x,const float* __restrict__ w,
                       const float* __restrict__ bias,
                       const float* __restrict__ gg,const float* __restrict__ bb){
    int t=threadIdx.x, jl=t>>6, b=t&63, j=blockIdx.x*4+jl;
    const float* wj=w+(size_t)j*F0;
    const float* xb=x+(size_t)b*F0;
    float s=bias[j];
    for(int r=0;r<F0;r++) s+=xb[r]*__ldg(wj+r);
    __shared__ float red[4][2];
    int wh=(t>>5)&1;
    float p=s;
    for(int o=16;o;o>>=1) p+=__shfl_xor_sync(0xffffffffu,p,o);
    if((t&31)==0) red[jl][wh]=p;
    __syncthreads();
    float m=(red[jl][0]+red[jl][1])*(1.f/64.f);
    __syncthreads();
    float d=s-m; p=d*d;
    for(int o=16;o;o>>=1) p+=__shfl_xor_sync(0xffffffffu,p,o);
    if((t&31)==0) red[jl][wh]=p;
    __syncthreads();
    float var=(red[jl][0]+red[jl][1])*(1.f/64.f);
    g_e0[b*256+j]=fmaxf(gg[j]*d*rsqrtf(var+EPSV)+bb[j],0.f);
}
__global__ void k_enc2(const float* __restrict__ w,const float* __restrict__ bias,
                       const float* __restrict__ gg,const float* __restrict__ bb){
    int t=threadIdx.x, jl=t>>6, b=t&63, j=blockIdx.x*4+jl;
    const float4* wj=(const float4*)(w+(size_t)j*256);
    const float4* xb=(const float4*)(g_e0+b*256);
    float s=bias[j];
#pragma unroll 8
    for(int r=0;r<64;r++){
        float4 a=xb[r], c=__ldg(wj+r);
        s+=a.x*c.x+a.y*c.y+a.z*c.z+a.w*c.w;
    }
    __shared__ float red[4][2];
    int wh=(t>>5)&1;
    float p=s;
    for(int o=16;o;o>>=1) p+=__shfl_xor_sync(0xffffffffu,p,o);
    if((t&31)==0) red[jl][wh]=p;
    __syncthreads();
    float m=(red[jl][0]+red[jl][1])*(1.f/64.f);
    __syncthreads();
    float d=s-m; p=d*d;
    for(int o=16;o;o>>=1) p+=__shfl_xor_sync(0xffffffffu,p,o);
    if((t&31)==0) red[jl][wh]=p;
    __syncthreads();
    float var=(red[jl][0]+red[jl][1])*(1.f/64.f);
    g_e1[(size_t)b*E1+j]=fmaxf(gg[j]*d*rsqrtf(var+EPSV)+bb[j],0.f);
}
__global__ void k_enc_head(const float* __restrict__ fc2_w,const float* __restrict__ fc2_b,
                           float* __restrict__ dist_out,float* __restrict__ loss_out){
    int b=blockIdx.x;
    __shared__ float es[E1];
    __shared__ float lg[LL];
    for(int j=threadIdx.x;j<E1;j+=blockDim.x) es[j]=g_e1[(size_t)b*E1+j];
    __syncthreads();
    if(threadIdx.x<LL){
        const float* w=fc2_w+(size_t)threadIdx.x*E1;
        float s=fc2_b[threadIdx.x];
        for(int j=0;j<E1;j++) s+=es[j]*__ldg(w+j);
        lg[threadIdx.x]=s;
    }
    __syncthreads();
    if(threadIdx.x==0){
        float loss=0.f;
        for(int v=0;v<6;v++){
            float mx=-1e30f;
            for(int k=0;k<6;k++) mx=fmaxf(mx,lg[v*6+k]);
            float ex[6],se=0.f;
            for(int k=0;k<6;k++){ex[k]=expf(lg[v*6+k]-mx);se+=ex[k];}
            float inv=1.f/se;
            for(int k=0;k<6;k++){
                float pp=ex[k]*inv;
                dist_out[b*LL+v*6+k]=pp;
                loss+=pp*logf(pp+1e-10f);
            }
        }
        loss_out[b]=0.1f*loss;
    }
}

// ------------------- GEMM1: round-11 core, thread-major epilogue -------------------
constexpr int G1_T=0, G1_AH=1024, G1_AL=G1_AH+9216, G1_BH=G1_AL+9216, G1_BL=G1_BH+36864;
constexpr int G1_SME=G1_BL+36864;   // 93184 B
__global__ void __launch_bounds__(256,2) k_gemm1(){
    extern __shared__ char sm[];
    int* tb=(int*)(sm+G1_T);
    const int t=threadIdx.x, wid=t>>5, lane=t&31, gid=lane>>2, tig=lane&3;
    const int n0=blockIdx.x*64;
    if(t<192){
        int r=t/3, c=t-r*3, n=n0+r;
        int val=(c==0)? (n/1296)%36 : (c==1)? 36+(n/36)%36 : 72+n%36;
        tb[t]=val*H1;
    }
    float acc[64];
#pragma unroll
    for(int i=0;i<64;i++) acc[i]=0.f;
    const int mrow0=(wid&3)*16, ncol0=(wid>>2)*128;

    for(int kc=0;kc<16;kc++){
        __syncthreads();
        const int kb=kc*64;
#pragma unroll
        for(int i=0;i<8;i++){
            int u=i*256+t, row=u>>3, part=u&7;
            cp16(sm+G1_BH+row*144+part*16,(const char*)g_W2nh+(size_t)row*2048+kb*2+part*16);
            cp16(sm+G1_BL+row*144+part*16,(const char*)g_W2nl+(size_t)row*2048+kb*2+part*16);
        }
        CP_COMMIT();
#pragma unroll
        for(int i=0;i<8;i++){
            int e=i*256+t, r=e>>5, l2=(e&31)*2, j=kb+l2;
            const int* tr=tb+r*3;
            float2 s0=*(const float2*)(g_T2+tr[0]+j);
            float2 s1=*(const float2*)(g_T2+tr[1]+j);
            float2 s2=*(const float2*)(g_T2+tr[2]+j);
            float va=fmaxf(s0.x+s1.x+s2.x,0.f), vb=fmaxf(s0.y+s1.y+s2.y,0.f);
            uint32_t hp=pack2(va,vb);
            float la=va-__uint_as_float(hp<<16), lb=vb-__uint_as_float(hp&0xffff0000u);
            uint32_t lp=pack2(la,lb);
            *(uint32_t*)(sm+G1_AH+r*144+l2*2)=hp;
            *(uint32_t*)(sm+G1_AL+r*144+l2*2)=lp;
        }
        CP_WAIT0();
        __syncthreads();
#pragma unroll
        for(int ks=0;ks<4;ks++){
            int ao=(mrow0+gid)*144+ks*32+tig*4;
            uint32_t ah[4],al[4];
            ah[0]=*(const uint32_t*)(sm+G1_AH+ao);
            ah[1]=*(const uint32_t*)(sm+G1_AH+ao+1152);
            ah[2]=*(const uint32_t*)(sm+G1_AH+ao+16);
            ah[3]=*(const uint32_t*)(sm+G1_AH+ao+1168);
            al[0]=*(const uint32_t*)(sm+G1_AL+ao);
            al[1]=*(const uint32_t*)(sm+G1_AL+ao+1152);
            al[2]=*(const uint32_t*)(sm+G1_AL+ao+16);
            al[3]=*(const uint32_t*)(sm+G1_AL+ao+1168);
#pragma unroll
            for(int g=0;g<16;g++){
                int bo=(ncol0+g*8+gid)*144+ks*32+tig*4;
                uint32_t bh0=*(const uint32_t*)(sm+G1_BH+bo);
                uint32_t bh1=*(const uint32_t*)(sm+G1_BH+bo+16);
                uint32_t bl0=*(const uint32_t*)(sm+G1_BL+bo);
                uint32_t bl1=*(const uint32_t*)(sm+G1_BL+bo+16);
                float* c=acc+g*4;
                mma16816(c,ah,bh0,bh1);
                mma16816(c,ah,bl0,bl1);
                mma16816(c,al,bh0,bh1);
            }
        }
    }
    // epilogue: relu+bias, split; store THREAD-MAJOR layout:
    // addr = row*512 + (col>>6)*128 + ((col>>1)&3)*32 + ((col>>4)&3)*8 + ((col>>3)&1)*4
    const int r0=n0+mrow0+gid;
#pragma unroll
    for(int nt=0;nt<16;nt++){
        int col=ncol0+nt*8+tig*2;
        float ba=g_b2f[col], bb2=g_b2f[col+1];
        size_t base=(size_t)(col>>6)*128+((col>>1)&3)*32+((col>>4)&3)*8+((col>>3)&1)*4;
        float v00=fmaxf(acc[nt*4+0]+ba,0.f), v01=fmaxf(acc[nt*4+1]+bb2,0.f);
        float v10=fmaxf(acc[nt*4+2]+ba,0.f), v11=fmaxf(acc[nt*4+3]+bb2,0.f);
        uint32_t hp=pack2(v00,v01);
        float la=v00-__uint_as_float(hp<<16), lb=v01-__uint_as_float(hp&0xffff0000u);
        *(uint32_t*)((char*)g_A2h+(size_t)r0*512+base)=hp;
        *(uint32_t*)((char*)g_A2l+(size_t)r0*512+base)=pack2(la,lb);
        hp=pack2(v10,v11);
        la=v10-__uint_as_float(hp<<16); lb=v11-__uint_as_float(hp&0xffff0000u);
        *(uint32_t*)((char*)g_A2h+(size_t)(r0+8)*512+base)=hp;
        *(uint32_t*)((char*)g_A2l+(size_t)(r0+8)*512+base)=pack2(la,lb);
    }
}

// ------------------- GEMM2: vectorized thread-major A loads -------------------
constexpr int G2_BH0=0, G2_BL0=16128, G2_BH1=32256, G2_BL1=48384;
constexpr int G2_SME=64512;
__global__ void __launch_bounds__(256,2)
k_gemm2(const float* __restrict__ dct2_w,const float* __restrict__ dct2_b){
    extern __shared__ char sm[];
    const int t=threadIdx.x, wid=t>>5, lane=t&31, gid=lane>>2, tig=lane&3;
    const int n0=blockIdx.x*128;
    const int s0=blockIdx.y, scnt=blockIdx.y? 3:4;
    float wv[12], b3v[4], dbv[3];
    {
        int ch0=tig*2;
        int chs[4]={ch0,ch0+1,8+ch0,9+ch0};
#pragma unroll
        for(int q=0;q<4;q++){
            b3v[q]=g_b3f[chs[q]];
#pragma unroll
            for(int o=0;o<3;o++) wv[q*3+o]=dct2_w[chs[q]*3+o];
        }
#pragma unroll
        for(int o=0;o<3;o++) dbv[o]=dct2_b[o];
    }
    const int row0=n0+wid*16+gid, row1=row0+8;
    const char* A0h=(const char*)g_A2h+(size_t)row0*512+tig*32;
    const char* A1h=(const char*)g_A2h+(size_t)row1*512+tig*32;
    const char* A0l=(const char*)g_A2l+(size_t)row0*512+tig*32;
    const char* A1l=(const char*)g_A2l+(size_t)row1*512+tig*32;

#define G2_STAGE(S,KC,BUF) do{ \
    int _bh=(BUF)? G2_BH1:G2_BH0, _bl=(BUF)? G2_BL1:G2_BL0; \
    _Pragma("unroll") \
    for(int _i=0;_i<7;_i++){ \
        int _u=_i*256+t; int _kind=_u>=896; int _uu=_kind? _u-896:_u; int _row=_uu>>3,_part=_uu&7; \
        const char* _src=(_kind? (const char*)g_W1nl:(const char*)g_W1nh)+(size_t)((S)*112+_row)*512+(KC)*128+_part*16; \
        cp16(sm+(_kind? _bl:_bh)+_row*144+_part*16,_src); \
    } CP_COMMIT(); }while(0)

    G2_STAGE(s0,0,0);
    CP_WAIT0();
    __syncthreads();
    int cc=0;
    for(int si=0;si<scnt;si++){
        int s=s0+si*2;
        float acc[56];
#pragma unroll
        for(int i=0;i<56;i++) acc[i]=0.f;
        for(int kc=0;kc<4;kc++){
            int buf=cc&1;
            if(cc+1<scnt*4){
                int nn=cc+1, s2=s0+(nn>>2)*2, kc2=nn&3;
                G2_STAGE(s2,kc2,buf^1);
            }
            int bh=buf? G2_BH1:G2_BH0, bl=buf? G2_BL1:G2_BL0;
#pragma unroll
            for(int kh=0;kh<2;kh++){
                uint4 qh=*(const uint4*)(A0h+kc*128+kh*16);
                uint4 rh=*(const uint4*)(A1h+kc*128+kh*16);
                uint4 ql=*(const uint4*)(A0l+kc*128+kh*16);
                uint4 rl=*(const uint4*)(A1l+kc*128+kh*16);
#pragma unroll
                for(int k2=0;k2<2;k2++){
                    const int ks=kh*2+k2;
                    uint32_t ah[4],al[4];
                    if(k2==0){
                        ah[0]=qh.x; ah[1]=rh.x; ah[2]=qh.y; ah[3]=rh.y;
                        al[0]=ql.x; al[1]=rl.x; al[2]=ql.y; al[3]=rl.y;
                    }else{
                        ah[0]=qh.z; ah[1]=rh.z; ah[2]=qh.w; ah[3]=rh.w;
                        al[0]=ql.z; al[1]=rl.z; al[2]=ql.w; al[3]=rl.w;
                    }
#pragma unroll
                    for(int g=0;g<14;g++){
                        int bo=(g*8+gid)*144+ks*32+tig*4;
                        uint32_t bh0=*(const uint32_t*)(sm+bh+bo);
                        uint32_t bh1=*(const uint32_t*)(sm+bh+bo+16);
                        uint32_t bl0=*(const uint32_t*)(sm+bl+bo);
                        uint32_t bl1=*(const uint32_t*)(sm+bl+bo+16);
                        float* c=acc+g*4;
                        mma16816(c,ah,bh0,bh1);
                        mma16816(c,ah,bl0,bl1);
                        mma16816(c,al,bh0,bh1);
                    }
                }
            }
            CP_WAIT0();
            __syncthreads();
            cc++;
        }
#pragma unroll
        for(int hw=0;hw<7;hw++){
            float hA0=fmaxf(acc[hw*8+0]+b3v[0],0.f);
            float hA1=fmaxf(acc[hw*8+1]+b3v[1],0.f);
            float hB0=fmaxf(acc[hw*8+4]+b3v[2],0.f);
            float hB1=fmaxf(acc[hw*8+5]+b3v[3],0.f);
            float hC0=fmaxf(acc[hw*8+2]+b3v[0],0.f);
            float hC1=fmaxf(acc[hw*8+3]+b3v[1],0.f);
            float hD0=fmaxf(acc[hw*8+6]+b3v[2],0.f);
            float hD1=fmaxf(acc[hw*8+7]+b3v[3],0.f);
            float p[6];
#pragma unroll
            for(int o=0;o<3;o++){
                p[o]  =hA0*wv[o]+hA1*wv[3+o]+hB0*wv[6+o]+hB1*wv[9+o];
                p[3+o]=hC0*wv[o]+hC1*wv[3+o]+hD0*wv[6+o]+hD1*wv[9+o];
            }
#pragma unroll
            for(int off=1;off<4;off<<=1)
#pragma unroll
                for(int q=0;q<6;q++) p[q]+=__shfl_xor_sync(0xffffffffu,p[q],off);
            if(tig<3){
                g_em[(size_t)row0*EMP+tig*49+s*7+hw]=p[tig]+dbv[tig];
                g_em[(size_t)row1*EMP+tig*49+s*7+hw]=p[3+tig]+dbv[tig];
            }
        }
    }
#undef G2_STAGE
}

// ------------------- obs: round-11 exact (ONB=96, occ 2, 4x4 tiles) -------------------
constexpr int ONB=96;
constexpr int OBS_SMEM=(ONB*EMP+64*EMP+ONB+64)*4;
__global__ void __launch_bounds__(256,2)
k_obs(const float* __restrict__ x,float* __restrict__ obs){
    extern __shared__ float smf[];
    float* ems=smf;
    float* xs=ems+ONB*EMP;
    float* s2s=xs+64*EMP;
    float* s1s=s2s+ONB;
    const int t=threadIdx.x, n0=blockIdx.x*ONB;
    {
        float4* dst=(float4*)ems;
        const float4* src=(const float4*)(g_em+(size_t)n0*EMP);
        for(int id=t;id<ONB*(EMP/4);id+=256) dst[id]=__ldg(src+id);
    }
    for(int id=t;id<64*F0;id+=256){
        int r=id/F0, c=id-r*F0;
        xs[r*EMP+c]=x[id];
    }
    if(t<64){ xs[t*EMP+F0]=0.f; s1s[t]=g_s1[t]; }
    __syncthreads();
    if(t<ONB){
        const float4* e=(const float4*)(ems+t*EMP);
        float s=0.f;
#pragma unroll 4
        for(int r=0;r<EMP/4;r++){
            float4 v=e[r];
            s+=v.x*v.x+v.y*v.y+v.z*v.z+v.w*v.w;
        }
        s2s[t]=s;
    }
    __syncthreads();
#pragma unroll
    for(int jj=0;jj<2;jj++){
        int tt=t+jj*256;
        if(tt<384){
            int bt=tt/24, nt=tt%24;
            const float4* xp0=(const float4*)(xs+(bt*4+0)*EMP);
            const float4* xp1=(const float4*)(xs+(bt*4+1)*EMP);
            const float4* xp2=(const float4*)(xs+(bt*4+2)*EMP);
            const float4* xp3=(const float4*)(xs+(bt*4+3)*EMP);
            const float4* e0=(const float4*)(ems+(nt*4+0)*EMP);
            const float4* e1=(const float4*)(ems+(nt*4+1)*EMP);
            const float4* e2=(const float4*)(ems+(nt*4+2)*EMP);
            const float4* e3=(const float4*)(ems+(nt*4+3)*EMP);
            float a[16];
#pragma unroll
            for(int i=0;i<16;i++) a[i]=0.f;
            for(int r=0;r<EMP/4;r++){
                float4 xv[4]={xp0[r],xp1[r],xp2[r],xp3[r]};
                float4 ev[4]={e0[r],e1[r],e2[r],e3[r]};
#pragma unroll
                for(int i=0;i<4;i++)
#pragma unroll
                    for(int k=0;k<4;k++)
                        a[i*4+k]+=xv[i].x*ev[k].x+xv[i].y*ev[k].y+xv[i].z*ev[k].z+xv[i].w*ev[k].w;
            }
#pragma unroll
            for(int i=0;i<4;i++){
                int b=bt*4+i;
                float4 o;
                o.x=-0.5f*(s2s[nt*4+0]-2.f*a[i*4+0]+s1s[b]);
                o.y=-0.5f*(s2s[nt*4+1]-2.f*a[i*4+1]+s1s[b]);
                o.z=-0.5f*(s2s[nt*4+2]-2.f*a[i*4+2]+s1s[b]);
                o.w=-0.5f*(s2s[nt*4+3]-2.f*a[i*4+3]+s1s[b]);
                *(float4*)(obs+(size_t)b*NN+n0+nt*4)=o;
            }
        }
    }
}

// ------------------- launch (round-11 order) -------------------
extern "C" void kernel_launch(void* const* d_in,const int* in_sizes,int n_in,
                              void* d_out,int out_size){
    const float* x     =(const float*)d_in[0];
    const float* conv_w=(const float*)d_in[1];
    const float* conv_b=(const float*)d_in[2];
    const float* ebn2_g=(const float*)d_in[3];
    const float* ebn2_b=(const float*)d_in[4];
    const float* fc1_w =(const float*)d_in[5];
    const float* fc1_b =(const float*)d_in[6];
    const float* ebn1_g=(const float*)d_in[7];
    const float* ebn1_b=(const float*)d_in[8];
    const float* fc2_w =(const float*)d_in[9];
    const float* fc2_b =(const float*)d_in[10];
    const float* embeds=(const float*)d_in[11];
    const float* dfc1_w=(const float*)d_in[12];
    const float* dfc1_b=(const float*)d_in[13];
    const float* dbn1_g=(const float*)d_in[14];
    const float* dbn1_b=(const float*)d_in[15];
    const float* dbn1_rm=(const float*)d_in[16];
    const float* dbn1_rv=(const float*)d_in[17];
    const float* dfc2_w=(const float*)d_in[18];
    const float* dfc2_b=(const float*)d_in[19];
    const float* dbn2_g=(const float*)d_in[20];
    const float* dbn2_b=(const float*)d_in[21];
    const float* dbn2_rm=(const float*)d_in[22];
    const float* dbn2_rv=(const float*)d_in[23];
    const float* dct1_w=(const float*)d_in[24];
    const float* dct1_b=(const float*)d_in[25];
    const float* dbn3_g=(const float*)d_in[26];
    const float* dbn3_b=(const float*)d_in[27];
    const float* dbn3_rm=(const float*)d_in[28];
    const float* dbn3_rv=(const float*)d_in[29];
    const float* dct2_w=(const float*)d_in[30];
    const float* dct2_b=(const float*)d_in[31];

    float* out=(float*)d_out;
    float* obs=out;
    float* dist=out+(size_t)Bb*NN;
    float* loss=dist+(size_t)Bb*LL;

    cudaFuncSetAttribute(k_gemm1,cudaFuncAttributeMaxDynamicSharedMemorySize,G1_SME);
    cudaFuncSetAttribute(k_gemm2,cudaFuncAttributeMaxDynamicSharedMemorySize,G2_SME);
    cudaFuncSetAttribute(k_obs,cudaFuncAttributeMaxDynamicSharedMemorySize,OBS_SMEM);

    k_prep<<<256,256>>>(x,embeds,dfc1_w,dfc1_b,dbn1_g,dbn1_b,dbn1_rm,dbn1_rv,
                        dfc2_w,dfc2_b,dbn2_g,dbn2_b,dbn2_rm,dbn2_rv,
                        dct1_w,dct1_b,dbn3_g,dbn3_b,dbn3_rm,dbn3_rv);
    k_prep_pairs<<<108,256>>>();
    k_gemm1<<<729,256,G1_SME>>>();
    k_gemm2<<<dim3(365,2),256,G2_SME>>>(dct2_w,dct2_b);
    k_enc1<<<64,256>>>(x,conv_w,conv_b,ebn2_g,ebn2_b);
    k_enc2<<<256,256>>>(fc1_w,fc1_b,ebn1_g,ebn1_b);
    k_enc_head<<<Bb,128>>>(fc2_w,fc2_b,dist,loss);
    k_obs<<<NN/ONB,256,OBS_SMEM>>>(x,obs);
}

// round 16
// speedup vs baseline: 5.8486x; 1.0378x over previous
#include <cuda_runtime.h>
#include <cuda_bf16.h>
#include <math.h>
#include <stdint.h>

#define EPSV 1e-5f
constexpr int Bb=64, NN=46656, F0=147, E1=1024, LL=36, H1=1024, H2=256, EMP=148;
constexpr int NPAD=46720;   // 365*128

__device__ float g_T[36*H1];
__device__ float g_T2[108*H1];          // pair tables, b1 folded into p=0
__device__ float g_b1[H1];
__device__ float g_b2f[H2];
__device__ float g_b3f[16];
__device__ float g_s1[Bb];
__device__ float g_e0[Bb*256];
__device__ float g_e1[Bb*E1];
__device__ __nv_bfloat16 g_W2nh[H2*H1];   // [o][j], bn2-scaled hi
__device__ __nv_bfloat16 g_W2nl[H2*H1];
__device__ __nv_bfloat16 g_W1nh[784*H2];  // [p'=hw*16+ch][i], bn3-scaled hi
__device__ __nv_bfloat16 g_W1nl[784*H2];
// thread-major MMA layout: row*512B + kc*128 + tig*32 + q*4  (q = k-pair slot)
__device__ __nv_bfloat16 g_A2h[(size_t)NPAD*256];
__device__ __nv_bfloat16 g_A2l[(size_t)NPAD*256];
__device__ float g_em[(size_t)NPAD*EMP];  // col 147 stays 0

__device__ __forceinline__ void bsplit(float v,__nv_bfloat16&hi,__nv_bfloat16&lo){
    hi=__float2bfloat16(v); lo=__float2bfloat16(v-__bfloat162float(hi));
}
__device__ __forceinline__ void mma16816(float* c,const uint32_t* a,uint32_t b0,uint32_t b1){
    asm volatile("mma.sync.aligned.m16n8k16.row.col.f32.bf16.bf16.f32 "
        "{%0,%1,%2,%3},{%4,%5,%6,%7},{%8,%9},{%0,%1,%2,%3};"
        :"+f"(c[0]),"+f"(c[1]),"+f"(c[2]),"+f"(c[3])
        :"r"(a[0]),"r"(a[1]),"r"(a[2]),"r"(a[3]),"r"(b0),"r"(b1));
}
__device__ __forceinline__ uint32_t pack2(float va,float vb){
    uint32_t hp; asm("cvt.rn.bf16x2.f32 %0,%1,%2;":"=r"(hp):"f"(vb),"f"(va)); return hp;
}
__device__ __forceinline__ void cp16(void* dst,const void* src){
    uint32_t d; asm("{ .reg .u64 t; cvta.to.shared.u64 t, %1; cvt.u32.u64 %0, t; }":"=r"(d):"l"(dst));
    asm volatile("cp.async.cg.shared.global [%0], [%1], 16;"::"r"(d),"l"(src):"memory");
}
#define CP_COMMIT() asm volatile("cp.async.commit_group;":::"memory")
#define CP_WAIT0()  asm volatile("cp.async.wait_group 0;":::"memory")

// ------------------- k_prep + pairs (round-11 exact) -------------------
__global__ void k_prep(
    const float* __restrict__ x,
    const float* __restrict__ embeds,const float* __restrict__ dfc1_w,
    const float* __restrict__ dfc1_b,const float* __restrict__ g1,const float* __restrict__ be1,
    const float* __restrict__ rm1,const float* __restrict__ rv1,
    const float* __restrict__ dfc2_w,const float* __restrict__ dfc2_b,
    const float* __restrict__ g2,const float* __restrict__ be2,
    const float* __restrict__ rm2,const float* __restrict__ rv2,
    const float* __restrict__ dct1_w,const float* __restrict__ dct1_b,
    const float* __restrict__ g3,const float* __restrict__ be3,
    const float* __restrict__ rm3,const float* __restrict__ rv3){
    int stride=gridDim.x*blockDim.x, tid=blockIdx.x*blockDim.x+threadIdx.x;
    for(int i=tid;i<36*H1;i+=stride){
        int m=i>>10, j=i&1023, v=m/6;
        const float* e=embeds+m*32;
        const float* w=dfc1_w+(size_t)j*192+v*32;
        float s=0.f;
#pragma unroll
        for(int d=0;d<32;d++) s+=e[d]*w[d];
        g_T[i]=g1[j]*rsqrtf(rv1[j]+EPSV)*s;
    }
    for(int j=tid;j<H1;j+=stride){
        float a=g1[j]*rsqrtf(rv1[j]+EPSV);
        g_b1[j]=a*(dfc1_b[j]-rm1[j])+be1[j];
    }
    for(int i=tid;i<H2*H1;i+=stride){
        int o=i>>10;
        float a=g2[o]*rsqrtf(rv2[o]+EPSV);
        __nv_bfloat16 hi,lo; bsplit(a*dfc2_w[i],hi,lo);
        g_W2nh[i]=hi; g_W2nl[i]=lo;
    }
    for(int o=tid;o<H2;o+=stride){
        float a=g2[o]*rsqrtf(rv2[o]+EPSV);
        g_b2f[o]=a*(dfc2_b[o]-rm2[o])+be2[o];
    }
    for(int e=tid;e<784*H2;e+=stride){
        int pcol=e>>8, i=e&255, hw=pcol>>4, ch=pcol&15;
        float a=g3[ch]*rsqrtf(rv3[ch]+EPSV);
        __nv_bfloat16 hi,lo; bsplit(a*dct1_w[i*784+ch*49+hw],hi,lo);
        g_W1nh[e]=hi; g_W1nl[e]=lo;
    }
    for(int o=tid;o<16;o+=stride){
        float a=g3[o]*rsqrtf(rv3[o]+EPSV);
        g_b3f[o]=a*(dct1_b[o]-rm3[o])+be3[o];
    }
    for(int b=tid;b<Bb;b+=stride){
        float s=0.f;
        for(int r=0;r<F0;r++){float v=x[b*F0+r];s+=v*v;}
        g_s1[b]=s;
    }
}
__global__ void k_prep_pairs(){
    int m=blockIdx.x;
    int p=m/36, ab=m%36, a=ab/6, b=ab%6;
    const float* ta=g_T+(p*12+a)*H1;
    const float* tbp=g_T+(p*12+6+b)*H1;
    float* dst=g_T2+(size_t)m*H1;
    for(int j=threadIdx.x;j<H1;j+=blockDim.x){
        float s=ta[j]+tbp[j];
        if(p==0) s+=g_b1[j];
        dst[j]=s;
    }
}

// ------------------- encoder (round-11 exact) -------------------
__global__ void k_enc1(const float* __restrict__ x,const float* __restrict__ w,
                       const float* __restrict__ bias,
                       const float* __restrict__ gg,const float* __restrict__ bb){
    int t=threadIdx.x, jl=t>>6, b=t&63, j=blockIdx.x*4+jl;
    const float* wj=w+(size_t)j*F0;
    const float* xb=x+(size_t)b*F0;
    float s=bias[j];
    for(int r=0;r<F0;r++) s+=xb[r]*__ldg(wj+r);
    __shared__ float red[4][2];
    int wh=(t>>5)&1;
    float p=s;
    for(int o=16;o;o>>=1) p+=__shfl_xor_sync(0xffffffffu,p,o);
    if((t&31)==0) red[jl][wh]=p;
    __syncthreads();
    float m=(red[jl][0]+red[jl][1])*(1.f/64.f);
    __syncthreads();
    float d=s-m; p=d*d;
    for(int o=16;o;o>>=1) p+=__shfl_xor_sync(0xffffffffu,p,o);
    if((t&31)==0) red[jl][wh]=p;
    __syncthreads();
    float var=(red[jl][0]+red[jl][1])*(1.f/64.f);
    g_e0[b*256+j]=fmaxf(gg[j]*d*rsqrtf(var+EPSV)+bb[j],0.f);
}
__global__ void k_enc2(const float* __restrict__ w,const float* __restrict__ bias,
                       const float* __restrict__ gg,const float* __restrict__ bb){
    int t=threadIdx.x, jl=t>>6, b=t&63, j=blockIdx.x*4+jl;
    const float4* wj=(const float4*)(w+(size_t)j*256);
    const float4* xb=(const float4*)(g_e0+b*256);
    float s=bias[j];
#pragma unroll 8
    for(int r=0;r<64;r++){
        float4 a=xb[r], c=__ldg(wj+r);
        s+=a.x*c.x+a.y*c.y+a.z*c.z+a.w*c.w;
    }
    __shared__ float red[4][2];
    int wh=(t>>5)&1;
    float p=s;
    for(int o=16;o;o>>=1) p+=__shfl_xor_sync(0xffffffffu,p,o);
    if((t&31)==0) red[jl][wh]=p;
    __syncthreads();
    float m=(red[jl][0]+red[jl][1])*(1.f/64.f);
    __syncthreads();
    float d=s-m; p=d*d;
    for(int o=16;o;o>>=1) p+=__shfl_xor_sync(0xffffffffu,p,o);
    if((t&31)==0) red[jl][wh]=p;
    __syncthreads();
    float var=(red[jl][0]+red[jl][1])*(1.f/64.f);
    g_e1[(size_t)b*E1+j]=fmaxf(gg[j]*d*rsqrtf(var+EPSV)+bb[j],0.f);
}
__global__ void k_enc_head(const float* __restrict__ fc2_w,const float* __restrict__ fc2_b,
                           float* __restrict__ dist_out,float* __restrict__ loss_out){
    int b=blockIdx.x;
    __shared__ float es[E1];
    __shared__ float lg[LL];
    for(int j=threadIdx.x;j<E1;j+=blockDim.x) es[j]=g_e1[(size_t)b*E1+j];
    __syncthreads();
    if(threadIdx.x<LL){
        const float* w=fc2_w+(size_t)threadIdx.x*E1;
        float s=fc2_b[threadIdx.x];
        for(int j=0;j<E1;j++) s+=es[j]*__ldg(w+j);
        lg[threadIdx.x]=s;
    }
    __syncthreads();
    if(threadIdx.x==0){
        float loss=0.f;
        for(int v=0;v<6;v++){
            float mx=-1e30f;
            for(int k=0;k<6;k++) mx=fmaxf(mx,lg[v*6+k]);
            float ex[6],se=0.f;
            for(int k=0;k<6;k++){ex[k]=expf(lg[v*6+k]-mx);se+=ex[k];}
            float inv=1.f/se;
            for(int k=0;k<6;k++){
                float pp=ex[k]*inv;
                dist_out[b*LL+v*6+k]=pp;
                loss+=pp*logf(pp+1e-10f);
            }
        }
        loss_out[b]=0.1f*loss;
    }
}

// ------------------- GEMM1: round-11 core, STG.128 thread-major epilogue ---------------
constexpr int G1_T=0, G1_AH=1024, G1_AL=G1_AH+9216, G1_BH=G1_AL+9216, G1_BL=G1_BH+36864;
constexpr int G1_SME=G1_BL+36864;   // 93184 B
__global__ void __launch_bounds__(256,2) k_gemm1(){
    extern __shared__ char sm[];
    int* tb=(int*)(sm+G1_T);
    const int t=threadIdx.x, wid=t>>5, lane=t&31, gid=lane>>2, tig=lane&3;
    const int n0=blockIdx.x*64;
    if(t<192){
        int r=t/3, c=t-r*3, n=n0+r;
        int val=(c==0)? (n/1296)%36 : (c==1)? 36+(n/36)%36 : 72+n%36;
        tb[t]=val*H1;
    }
    float acc[64];
#pragma unroll
    for(int i=0;i<64;i++) acc[i]=0.f;
    const int mrow0=(wid&3)*16, ncol0=(wid>>2)*128;

    for(int kc=0;kc<16;kc++){
        __syncthreads();
        const int kb=kc*64;
#pragma unroll
        for(int i=0;i<8;i++){
            int u=i*256+t, row=u>>3, part=u&7;
            cp16(sm+G1_BH+row*144+part*16,(const char*)g_W2nh+(size_t)row*2048+kb*2+part*16);
            cp16(sm+G1_BL+row*144+part*16,(const char*)g_W2nl+(size_t)row*2048+kb*2+part*16);
        }
        CP_COMMIT();
#pragma unroll
        for(int i=0;i<8;i++){
            int e=i*256+t, r=e>>5, l2=(e&31)*2, j=kb+l2;
            const int* tr=tb+r*3;
            float2 s0=*(const float2*)(g_T2+tr[0]+j);
            float2 s1=*(const float2*)(g_T2+tr[1]+j);
            float2 s2=*(const float2*)(g_T2+tr[2]+j);
            float va=fmaxf(s0.x+s1.x+s2.x,0.f), vb=fmaxf(s0.y+s1.y+s2.y,0.f);
            uint32_t hp=pack2(va,vb);
            float la=va-__uint_as_float(hp<<16), lb=vb-__uint_as_float(hp&0xffff0000u);
            uint32_t lp=pack2(la,lb);
            *(uint32_t*)(sm+G1_AH+r*144+l2*2)=hp;
            *(uint32_t*)(sm+G1_AL+r*144+l2*2)=lp;
        }
        CP_WAIT0();
        __syncthreads();
#pragma unroll
        for(int ks=0;ks<4;ks++){
            int ao=(mrow0+gid)*144+ks*32+tig*4;
            uint32_t ah[4],al[4];
            ah[0]=*(const uint32_t*)(sm+G1_AH+ao);
            ah[1]=*(const uint32_t*)(sm+G1_AH+ao+1152);
            ah[2]=*(const uint32_t*)(sm+G1_AH+ao+16);
            ah[3]=*(const uint32_t*)(sm+G1_AH+ao+1168);
            al[0]=*(const uint32_t*)(sm+G1_AL+ao);
            al[1]=*(const uint32_t*)(sm+G1_AL+ao+1152);
            al[2]=*(const uint32_t*)(sm+G1_AL+ao+16);
            al[3]=*(const uint32_t*)(sm+G1_AL+ao+1168);
#pragma unroll
            for(int g=0;g<16;g++){
                int bo=(ncol0+g*8+gid)*144+ks*32+tig*4;
                uint32_t bh0=*(const uint32_t*)(sm+G1_BH+bo);
                uint32_t bh1=*(const uint32_t*)(sm+G1_BH+bo+16);
                uint32_t bl0=*(const uint32_t*)(sm+G1_BL+bo);
                uint32_t bl1=*(const uint32_t*)(sm+G1_BL+bo+16);
                float* c=acc+g*4;
                mma16816(c,ah,bh0,bh1);
                mma16816(c,ah,bl0,bl1);
                mma16816(c,al,bh0,bh1);
            }
        }
    }
    // epilogue: relu+bias, split; buffered STG.128 into thread-major layout
    // slot q=nt&7 at row*512 + kc*128 + tig*32 + q*4 (contiguous 32B per row/kc)
    const int r0=n0+mrow0+gid;
#pragma unroll
    for(int kcg=0;kcg<2;kcg++){
        uint32_t h0[8],l0[8],h1[8],l1[8];
#pragma unroll
        for(int q=0;q<8;q++){
            int nt=kcg*8+q;
            int col=ncol0+nt*8+tig*2;
            float ba=g_b2f[col], bb2=g_b2f[col+1];
            float v00=fmaxf(acc[nt*4+0]+ba,0.f), v01=fmaxf(acc[nt*4+1]+bb2,0.f);
            float v10=fmaxf(acc[nt*4+2]+ba,0.f), v11=fmaxf(acc[nt*4+3]+bb2,0.f);
            uint32_t hp=pack2(v00,v01);
            h0[q]=hp;
            l0[q]=pack2(v00-__uint_as_float(hp<<16),v01-__uint_as_float(hp&0xffff0000u));
            hp=pack2(v10,v11);
            h1[q]=hp;
            l1[q]=pack2(v10-__uint_as_float(hp<<16),v11-__uint_as_float(hp&0xffff0000u));
        }
        size_t base0=(size_t)r0*512+(size_t)((ncol0>>6)+kcg)*128+tig*32;
        size_t base1=base0+(size_t)8*512;
        *(uint4*)((char*)g_A2h+base0)=*(uint4*)h0;
        *(uint4*)((char*)g_A2h+base0+16)=*(uint4*)(h0+4);
        *(uint4*)((char*)g_A2l+base0)=*(uint4*)l0;
        *(uint4*)((char*)g_A2l+base0+16)=*(uint4*)(l0+4);
        *(uint4*)((char*)g_A2h+base1)=*(uint4*)h1;
        *(uint4*)((char*)g_A2h+base1+16)=*(uint4*)(h1+4);
        *(uint4*)((char*)g_A2l+base1)=*(uint4*)l1;
        *(uint4*)((char*)g_A2l+base1+16)=*(uint4*)(l1+4);
    }
}

// ------------------- GEMM2: round-15 exact (vectorized thread-major A loads) ----------
constexpr int G2_BH0=0, G2_BL0=16128, G2_BH1=32256, G2_BL1=48384;
constexpr int G2_SME=64512;
__global__ void __launch_bounds__(256,2)
k_gemm2(const float* __restrict__ dct2_w,const float* __restrict__ dct2_b){
    extern __shared__ char sm[];
    const int t=threadIdx.x, wid=t>>5, lane=t&31, gid=lane>>2, tig=lane&3;
    const int n0=blockIdx.x*128;
    const int s0=blockIdx.y, scnt=blockIdx.y? 3:4;
    float wv[12], b3v[4], dbv[3];
    {
        int ch0=tig*2;
        int chs[4]={ch0,ch0+1,8+ch0,9+ch0};
#pragma unroll
        for(int q=0;q<4;q++){
            b3v[q]=g_b3f[chs[q]];
#pragma unroll
            for(int o=0;o<3;o++) wv[q*3+o]=dct2_w[chs[q]*3+o];
        }
#pragma unroll
        for(int o=0;o<3;o++) dbv[o]=dct2_b[o];
    }
    const int row0=n0+wid*16+gid, row1=row0+8;
    const char* A0h=(const char*)g_A2h+(size_t)row0*512+tig*32;
    const char* A1h=(const char*)g_A2h+(size_t)row1*512+tig*32;
    const char* A0l=(const char*)g_A2l+(size_t)row0*512+tig*32;
    const char* A1l=(const char*)g_A2l+(size_t)row1*512+tig*32;

#define G2_STAGE(S,KC,BUF) do{ \
    int _bh=(BUF)? G2_BH1:G2_BH0, _bl=(BUF)? G2_BL1:G2_BL0; \
    _Pragma("unroll") \
    for(int _i=0;_i<7;_i++){ \
        int _u=_i*256+t; int _kind=_u>=896; int _uu=_kind? _u-896:_u; int _row=_uu>>3,_part=_uu&7; \
        const char* _src=(_kind? (const char*)g_W1nl:(const char*)g_W1nh)+(size_t)((S)*112+_row)*512+(KC)*128+_part*16; \
        cp16(sm+(_kind? _bl:_bh)+_row*144+_part*16,_src); \
    } CP_COMMIT(); }while(0)

    G2_STAGE(s0,0,0);
    CP_WAIT0();
    __syncthreads();
    int cc=0;
    for(int si=0;si<scnt;si++){
        int s=s0+si*2;
        float acc[56];
#pragma unroll
        for(int i=0;i<56;i++) acc[i]=0.f;
        for(int kc=0;kc<4;kc++){
            int buf=cc&1;
            if(cc+1<scnt*4){
                int nn=cc+1, s2=s0+(nn>>2)*2, kc2=nn&3;
                G2_STAGE(s2,kc2,buf^1);
            }
            int bh=buf? G2_BH1:G2_BH0, bl=buf? G2_BL1:G2_BL0;
#pragma unroll
            for(int kh=0;kh<2;kh++){
                uint4 qh=*(const uint4*)(A0h+kc*128+kh*16);
                uint4 rh=*(const uint4*)(A1h+kc*128+kh*16);
                uint4 ql=*(const uint4*)(A0l+kc*128+kh*16);
                uint4 rl=*(const uint4*)(A1l+kc*128+kh*16);
#pragma unroll
                for(int k2=0;k2<2;k2++){
                    const int ks=kh*2+k2;
                    uint32_t ah[4],al[4];
                    if(k2==0){
                        ah[0]=qh.x; ah[1]=rh.x; ah[2]=qh.y; ah[3]=rh.y;
                        al[0]=ql.x; al[1]=rl.x; al[2]=ql.y; al[3]=rl.y;
                    }else{
                        ah[0]=qh.z; ah[1]=rh.z; ah[2]=qh.w; ah[3]=rh.w;
                        al[0]=ql.z; al[1]=rl.z; al[2]=ql.w; al[3]=rl.w;
                    }
#pragma unroll
                    for(int g=0;g<14;g++){
                        int bo=(g*8+gid)*144+ks*32+tig*4;
                        uint32_t bh0=*(const uint32_t*)(sm+bh+bo);
                        uint32_t bh1=*(const uint32_t*)(sm+bh+bo+16);
                        uint32_t bl0=*(const uint32_t*)(sm+bl+bo);
                        uint32_t bl1=*(const uint32_t*)(sm+bl+bo+16);
                        float* c=acc+g*4;
                        mma16816(c,ah,bh0,bh1);
                        mma16816(c,ah,bl0,bl1);
                        mma16816(c,al,bh0,bh1);
                    }
                }
            }
            CP_WAIT0();
            __syncthreads();
            cc++;
        }
#pragma unroll
        for(int hw=0;hw<7;hw++){
            float hA0=fmaxf(acc[hw*8+0]+b3v[0],0.f);
            float hA1=fmaxf(acc[hw*8+1]+b3v[1],0.f);
            float hB0=fmaxf(acc[hw*8+4]+b3v[2],0.f);
            float hB1=fmaxf(acc[hw*8+5]+b3v[3],0.f);
            float hC0=fmaxf(acc[hw*8+2]+b3v[0],0.f);
            float hC1=fmaxf(acc[hw*8+3]+b3v[1],0.f);
            float hD0=fmaxf(acc[hw*8+6]+b3v[2],0.f);
            float hD1=fmaxf(acc[hw*8+7]+b3v[3],0.f);
            float p[6];
#pragma unroll
            for(int o=0;o<3;o++){
                p[o]  =hA0*wv[o]+hA1*wv[3+o]+hB0*wv[6+o]+hB1*wv[9+o];
                p[3+o]=hC0*wv[o]+hC1*wv[3+o]+hD0*wv[6+o]+hD1*wv[9+o];
            }
#pragma unroll
            for(int off=1;off<4;off<<=1)
#pragma unroll
                for(int q=0;q<6;q++) p[q]+=__shfl_xor_sync(0xffffffffu,p[q],off);
            if(tig<3){
                g_em[(size_t)row0*EMP+tig*49+s*7+hw]=p[tig]+dbv[tig];
                g_em[(size_t)row1*EMP+tig*49+s*7+hw]=p[3+tig]+dbv[tig];
            }
        }
    }
#undef G2_STAGE
}

// ------------------- obs: round-11 exact (ONB=96, occ 2, 4x4 tiles) -------------------
constexpr int ONB=96;
constexpr int OBS_SMEM=(ONB*EMP+64*EMP+ONB+64)*4;
__global__ void __launch_bounds__(256,2)
k_obs(const float* __restrict__ x,float* __restrict__ obs){
    extern __shared__ float smf[];
    float* ems=smf;
    float* xs=ems+ONB*EMP;
    float* s2s=xs+64*EMP;
    float* s1s=s2s+ONB;
    const int t=threadIdx.x, n0=blockIdx.x*ONB;
    {
        float4* dst=(float4*)ems;
        const float4* src=(const float4*)(g_em+(size_t)n0*EMP);
        for(int id=t;id<ONB*(EMP/4);id+=256) dst[id]=__ldg(src+id);
    }
    for(int id=t;id<64*F0;id+=256){
        int r=id/F0, c=id-r*F0;
        xs[r*EMP+c]=x[id];
    }
    if(t<64){ xs[t*EMP+F0]=0.f; s1s[t]=g_s1[t]; }
    __syncthreads();
    if(t<ONB){
        const float4* e=(const float4*)(ems+t*EMP);
        float s=0.f;
#pragma unroll 4
        for(int r=0;r<EMP/4;r++){
            float4 v=e[r];
            s+=v.x*v.x+v.y*v.y+v.z*v.z+v.w*v.w;
        }
        s2s[t]=s;
    }
    __syncthreads();
#pragma unroll
    for(int jj=0;jj<2;jj++){
        int tt=t+jj*256;
        if(tt<384){
            int bt=tt/24, nt=tt%24;
            const float4* xp0=(const float4*)(xs+(bt*4+0)*EMP);
            const float4* xp1=(const float4*)(xs+(bt*4+1)*EMP);
            const float4* xp2=(const float4*)(xs+(bt*4+2)*EMP);
            const float4* xp3=(const float4*)(xs+(bt*4+3)*EMP);
            const float4* e0=(const float4*)(ems+(nt*4+0)*EMP);
            const float4* e1=(const float4*)(ems+(nt*4+1)*EMP);
            const float4* e2=(const float4*)(ems+(nt*4+2)*EMP);
            const float4* e3=(const float4*)(ems+(nt*4+3)*EMP);
            float a[16];
#pragma unroll
            for(int i=0;i<16;i++) a[i]=0.f;
            for(int r=0;r<EMP/4;r++){
                float4 xv[4]={xp0[r],xp1[r],xp2[r],xp3[r]};
                float4 ev[4]={e0[r],e1[r],e2[r],e3[r]};
#pragma unroll
                for(int i=0;i<4;i++)
#pragma unroll
                    for(int k=0;k<4;k++)
                        a[i*4+k]+=xv[i].x*ev[k].x+xv[i].y*ev[k].y+xv[i].z*ev[k].z+xv[i].w*ev[k].w;
            }
#pragma unroll
            for(int i=0;i<4;i++){
                int b=bt*4+i;
                float4 o;
                o.x=-0.5f*(s2s[nt*4+0]-2.f*a[i*4+0]+s1s[b]);
                o.y=-0.5f*(s2s[nt*4+1]-2.f*a[i*4+1]+s1s[b]);
                o.z=-0.5f*(s2s[nt*4+2]-2.f*a[i*4+2]+s1s[b]);
                o.w=-0.5f*(s2s[nt*4+3]-2.f*a[i*4+3]+s1s[b]);
                *(float4*)(obs+(size_t)b*NN+n0+nt*4)=o;
            }
        }
    }
}

// ------------------- launch (round-11 order) -------------------
extern "C" void kernel_launch(void* const* d_in,const int* in_sizes,int n_in,
                              void* d_out,int out_size){
    const float* x     =(const float*)d_in[0];
    const float* conv_w=(const float*)d_in[1];
    const float* conv_b=(const float*)d_in[2];
    const float* ebn2_g=(const float*)d_in[3];
    const float* ebn2_b=(const float*)d_in[4];
    const float* fc1_w =(const float*)d_in[5];
    const float* fc1_b =(const float*)d_in[6];
    const float* ebn1_g=(const float*)d_in[7];
    const float* ebn1_b=(const float*)d_in[8];
    const float* fc2_w =(const float*)d_in[9];
    const float* fc2_b =(const float*)d_in[10];
    const float* embeds=(const float*)d_in[11];
    const float* dfc1_w=(const float*)d_in[12];
    const float* dfc1_b=(const float*)d_in[13];
    const float* dbn1_g=(const float*)d_in[14];
    const float* dbn1_b=(const float*)d_in[15];
    const float* dbn1_rm=(const float*)d_in[16];
    const float* dbn1_rv=(const float*)d_in[17];
    const float* dfc2_w=(const float*)d_in[18];
    const float* dfc2_b=(const float*)d_in[19];
    const float* dbn2_g=(const float*)d_in[20];
    const float* dbn2_b=(const float*)d_in[21];
    const float* dbn2_rm=(const float*)d_in[22];
    const float* dbn2_rv=(const float*)d_in[23];
    const float* dct1_w=(const float*)d_in[24];
    const float* dct1_b=(const float*)d_in[25];
    const float* dbn3_g=(const float*)d_in[26];
    const float* dbn3_b=(const float*)d_in[27];
    const float* dbn3_rm=(const float*)d_in[28];
    const float* dbn3_rv=(const float*)d_in[29];
    const float* dct2_w=(const float*)d_in[30];
    const float* dct2_b=(const float*)d_in[31];

    float* out=(float*)d_out;
    float* obs=out;
    float* dist=out+(size_t)Bb*NN;
    float* loss=dist+(size_t)Bb*LL;

    cudaFuncSetAttribute(k_gemm1,cudaFuncAttributeMaxDynamicSharedMemorySize,G1_SME);
    cudaFuncSetAttribute(k_gemm2,cudaFuncAttributeMaxDynamicSharedMemorySize,G2_SME);
    cudaFuncSetAttribute(k_obs,cudaFuncAttributeMaxDynamicSharedMemorySize,OBS_SMEM);

    k_prep<<<256,256>>>(x,embeds,dfc1_w,dfc1_b,dbn1_g,dbn1_b,dbn1_rm,dbn1_rv,
                        dfc2_w,dfc2_b,dbn2_g,dbn2_b,dbn2_rm,dbn2_rv,
                        dct1_w,dct1_b,dbn3_g,dbn3_b,dbn3_rm,dbn3_rv);
    k_prep_pairs<<<108,256>>>();
    k_gemm1<<<729,256,G1_SME>>>();
    k_gemm2<<<dim3(365,2),256,G2_SME>>>(dct2_w,dct2_b);
    k_enc1<<<64,256>>>(x,conv_w,conv_b,ebn2_g,ebn2_b);
    k_enc2<<<256,256>>>(fc1_w,fc1_b,ebn1_g,ebn1_b);
    k_enc_head<<<Bb,128>>>(fc2_w,fc2_b,dist,loss);
    k_obs<<<NN/ONB,256,OBS_SMEM>>>(x,obs);
}

// round 17
// speedup vs baseline: 6.2116x; 1.0621x over previous
#include <cuda_runtime.h>
#include <cuda_bf16.h>
#include <math.h>
#include <stdint.h>

#define EPSV 1e-5f
constexpr int Bb=64, NN=46656, F0=147, E1=1024, LL=36, H1=1024, H2=256, EMP=148;
constexpr int NPAD=46720;   // 365*128

__device__ float g_T[36*H1];
__device__ float g_T2[108*H1];
__device__ float g_b1[H1];
__device__ float g_b2f[H2];
__device__ float g_b3f[16];
__device__ float g_s1[Bb];
__device__ float g_e0[Bb*256];
__device__ float g_e1[Bb*E1];
__device__ __nv_bfloat16 g_W2nh[H2*H1];
__device__ __nv_bfloat16 g_W2nl[H2*H1];
__device__ __nv_bfloat16 g_W1nh[784*H2];
__device__ __nv_bfloat16 g_W1nl[784*H2];
// thread-major MMA layout: row*512B + kc*128 + tig*32 + q*4
__device__ __nv_bfloat16 g_A2h[(size_t)NPAD*256];
__device__ __nv_bfloat16 g_A2l[(size_t)NPAD*256];
__device__ float g_em[(size_t)NPAD*EMP];

__device__ __forceinline__ void bsplit(float v,__nv_bfloat16&hi,__nv_bfloat16&lo){
    hi=__float2bfloat16(v); lo=__float2bfloat16(v-__bfloat162float(hi));
}
__device__ __forceinline__ void mma16816(float* c,const uint32_t* a,uint32_t b0,uint32_t b1){
    asm volatile("mma.sync.aligned.m16n8k16.row.col.f32.bf16.bf16.f32 "
        "{%0,%1,%2,%3},{%4,%5,%6,%7},{%8,%9},{%0,%1,%2,%3};"
        :"+f"(c[0]),"+f"(c[1]),"+f"(c[2]),"+f"(c[3])
        :"r"(a[0]),"r"(a[1]),"r"(a[2]),"r"(a[3]),"r"(b0),"r"(b1));
}
__device__ __forceinline__ uint32_t pack2(float va,float vb){
    uint32_t hp; asm("cvt.rn.bf16x2.f32 %0,%1,%2;":"=r"(hp):"f"(vb),"f"(va)); return hp;
}
__device__ __forceinline__ void cp16(void* dst,const void* src){
    uint32_t d; asm("{ .reg .u64 t; cvta.to.shared.u64 t, %1; cvt.u32.u64 %0, t; }":"=r"(d):"l"(dst));
    asm volatile("cp.async.cg.shared.global [%0], [%1], 16;"::"r"(d),"l"(src):"memory");
}
#define CP_COMMIT() asm volatile("cp.async.commit_group;":::"memory")
#define CP_WAIT0()  asm volatile("cp.async.wait_group 0;":::"memory")

// ------------------- k_prep (round-11 exact) -------------------
__global__ void k_prep(
    const float* __restrict__ x,
    const float* __restrict__ embeds,const float* __restrict__ dfc1_w,
    const float* __restrict__ dfc1_b,const float* __restrict__ g1,const float* __restrict__ be1,
    const float* __restrict__ rm1,const float* __restrict__ rv1,
    const float* __restrict__ dfc2_w,const float* __restrict__ dfc2_b,
    const float* __restrict__ g2,const float* __restrict__ be2,
    const float* __restrict__ rm2,const float* __restrict__ rv2,
    const float* __restrict__ dct1_w,const float* __restrict__ dct1_b,
    const float* __restrict__ g3,const float* __restrict__ be3,
    const float* __restrict__ rm3,const float* __restrict__ rv3){
    int stride=gridDim.x*blockDim.x, tid=blockIdx.x*blockDim.x+threadIdx.x;
    for(int i=tid;i<36*H1;i+=stride){
        int m=i>>10, j=i&1023, v=m/6;
        const float* e=embeds+m*32;
        const float* w=dfc1_w+(size_t)j*192+v*32;
        float s=0.f;
#pragma unroll
        for(int d=0;d<32;d++) s+=e[d]*w[d];
        g_T[i]=g1[j]*rsqrtf(rv1[j]+EPSV)*s;
    }
    for(int j=tid;j<H1;j+=stride){
        float a=g1[j]*rsqrtf(rv1[j]+EPSV);
        g_b1[j]=a*(dfc1_b[j]-rm1[j])+be1[j];
    }
    for(int i=tid;i<H2*H1;i+=stride){
        int o=i>>10;
        float a=g2[o]*rsqrtf(rv2[o]+EPSV);
        __nv_bfloat16 hi,lo; bsplit(a*dfc2_w[i],hi,lo);
        g_W2nh[i]=hi; g_W2nl[i]=lo;
    }
    for(int o=tid;o<H2;o+=stride){
        float a=g2[o]*rsqrtf(rv2[o]+EPSV);
        g_b2f[o]=a*(dfc2_b[o]-rm2[o])+be2[o];
    }
    for(int e=tid;e<784*H2;e+=stride){
        int pcol=e>>8, i=e&255, hw=pcol>>4, ch=pcol&15;
        float a=g3[ch]*rsqrtf(rv3[ch]+EPSV);
        __nv_bfloat16 hi,lo; bsplit(a*dct1_w[i*784+ch*49+hw],hi,lo);
        g_W1nh[e]=hi; g_W1nl[e]=lo;
    }
    for(int o=tid;o<16;o+=stride){
        float a=g3[o]*rsqrtf(rv3[o]+EPSV);
        g_b3f[o]=a*(dct1_b[o]-rm3[o])+be3[o];
    }
    for(int b=tid;b<Bb;b+=stride){
        float s=0.f;
        for(int r=0;r<F0;r++){float v=x[b*F0+r];s+=v*v;}
        g_s1[b]=s;
    }
}

// ------------------- k_prep_pairs + enc1 (blocks 108..171) -------------------
__global__ void k_prep_pairs(const float* __restrict__ x,const float* __restrict__ conv_w,
                             const float* __restrict__ conv_b,
                             const float* __restrict__ eg,const float* __restrict__ eb){
    if(blockIdx.x<108){
        int m=blockIdx.x;
        int p=m/36, ab=m%36, a=ab/6, b=ab%6;
        const float* ta=g_T+(p*12+a)*H1;
        const float* tbp=g_T+(p*12+6+b)*H1;
        float* dst=g_T2+(size_t)m*H1;
        for(int j=threadIdx.x;j<H1;j+=blockDim.x){
            float s=ta[j]+tbp[j];
            if(p==0) s+=g_b1[j];
            dst[j]=s;
        }
        return;
    }
    // enc1 (round-11 body)
    int t=threadIdx.x, jl=t>>6, b=t&63, j=(blockIdx.x-108)*4+jl;
    const float* wj=conv_w+(size_t)j*F0;
    const float* xb=x+(size_t)b*F0;
    float s=conv_b[j];
    for(int r=0;r<F0;r++) s+=xb[r]*__ldg(wj+r);
    __shared__ float red[4][2];
    int wh=(t>>5)&1;
    float p=s;
    for(int o=16;o;o>>=1) p+=__shfl_xor_sync(0xffffffffu,p,o);
    if((t&31)==0) red[jl][wh]=p;
    __syncthreads();
    float m=(red[jl][0]+red[jl][1])*(1.f/64.f);
    __syncthreads();
    float d=s-m; p=d*d;
    for(int o=16;o;o>>=1) p+=__shfl_xor_sync(0xffffffffu,p,o);
    if((t&31)==0) red[jl][wh]=p;
    __syncthreads();
    float var=(red[jl][0]+red[jl][1])*(1.f/64.f);
    g_e0[b*256+j]=fmaxf(eg[j]*d*rsqrtf(var+EPSV)+eb[j],0.f);
}

// ------------------- GEMM1 + enc2 (blocks 729..984) -------------------
constexpr int G1_T=0, G1_AH=1024, G1_AL=G1_AH+9216, G1_BH=G1_AL+9216, G1_BL=G1_BH+36864;
constexpr int G1_SME=G1_BL+36864;   // 93184 B
__global__ void __launch_bounds__(256,2)
k_gemm1(const float* __restrict__ fc1_w,const float* __restrict__ fc1_b,
        const float* __restrict__ eg1,const float* __restrict__ eb1){
    extern __shared__ char sm[];
    const int t=threadIdx.x;
    if(blockIdx.x>=729){
        // enc2 (round-11 body)
        int jl=t>>6, b=t&63, j=(blockIdx.x-729)*4+jl;
        const float4* wj=(const float4*)(fc1_w+(size_t)j*256);
        const float4* xb=(const float4*)(g_e0+b*256);
        float s=fc1_b[j];
#pragma unroll 8
        for(int r=0;r<64;r++){
            float4 a=xb[r], c=__ldg(wj+r);
            s+=a.x*c.x+a.y*c.y+a.z*c.z+a.w*c.w;
        }
        __shared__ float red[4][2];
        int wh=(t>>5)&1;
        float p=s;
        for(int o=16;o;o>>=1) p+=__shfl_xor_sync(0xffffffffu,p,o);
        if((t&31)==0) red[jl][wh]=p;
        __syncthreads();
        float m=(red[jl][0]+red[jl][1])*(1.f/64.f);
        __syncthreads();
        float d=s-m; p=d*d;
        for(int o=16;o;o>>=1) p+=__shfl_xor_sync(0xffffffffu,p,o);
        if((t&31)==0) red[jl][wh]=p;
        __syncthreads();
        float var=(red[jl][0]+red[jl][1])*(1.f/64.f);
        g_e1[(size_t)b*E1+j]=fmaxf(eg1[j]*d*rsqrtf(var+EPSV)+eb1[j],0.f);
        return;
    }
    int* tb=(int*)(sm+G1_T);
    const int wid=t>>5, lane=t&31, gid=lane>>2, tig=lane&3;
    const int n0=blockIdx.x*64;
    if(t<192){
        int r=t/3, c=t-r*3, n=n0+r;
        int val=(c==0)? (n/1296)%36 : (c==1)? 36+(n/36)%36 : 72+n%36;
        tb[t]=val*H1;
    }
    float acc[64];
#pragma unroll
    for(int i=0;i<64;i++) acc[i]=0.f;
    const int mrow0=(wid&3)*16, ncol0=(wid>>2)*128;

    for(int kc=0;kc<16;kc++){
        __syncthreads();
        const int kb=kc*64;
#pragma unroll
        for(int i=0;i<8;i++){
            int u=i*256+t, row=u>>3, part=u&7;
            cp16(sm+G1_BH+row*144+part*16,(const char*)g_W2nh+(size_t)row*2048+kb*2+part*16);
            cp16(sm+G1_BL+row*144+part*16,(const char*)g_W2nl+(size_t)row*2048+kb*2+part*16);
        }
        CP_COMMIT();
#pragma unroll
        for(int i=0;i<8;i++){
            int e=i*256+t, r=e>>5, l2=(e&31)*2, j=kb+l2;
            const int* tr=tb+r*3;
            float2 s0=*(const float2*)(g_T2+tr[0]+j);
            float2 s1=*(const float2*)(g_T2+tr[1]+j);
            float2 s2=*(const float2*)(g_T2+tr[2]+j);
            float va=fmaxf(s0.x+s1.x+s2.x,0.f), vb=fmaxf(s0.y+s1.y+s2.y,0.f);
            uint32_t hp=pack2(va,vb);
            float la=va-__uint_as_float(hp<<16), lb=vb-__uint_as_float(hp&0xffff0000u);
            uint32_t lp=pack2(la,lb);
            *(uint32_t*)(sm+G1_AH+r*144+l2*2)=hp;
            *(uint32_t*)(sm+G1_AL+r*144+l2*2)=lp;
        }
        CP_WAIT0();
        __syncthreads();
#pragma unroll
        for(int ks=0;ks<4;ks++){
            int ao=(mrow0+gid)*144+ks*32+tig*4;
            uint32_t ah[4],al[4];
            ah[0]=*(const uint32_t*)(sm+G1_AH+ao);
            ah[1]=*(const uint32_t*)(sm+G1_AH+ao+1152);
            ah[2]=*(const uint32_t*)(sm+G1_AH+ao+16);
            ah[3]=*(const uint32_t*)(sm+G1_AH+ao+1168);
            al[0]=*(const uint32_t*)(sm+G1_AL+ao);
            al[1]=*(const uint32_t*)(sm+G1_AL+ao+1152);
            al[2]=*(const uint32_t*)(sm+G1_AL+ao+16);
            al[3]=*(const uint32_t*)(sm+G1_AL+ao+1168);
#pragma unroll
            for(int g=0;g<16;g++){
                int bo=(ncol0+g*8+gid)*144+ks*32+tig*4;
                uint32_t bh0=*(const uint32_t*)(sm+G1_BH+bo);
                uint32_t bh1=*(const uint32_t*)(sm+G1_BH+bo+16);
                uint32_t bl0=*(const uint32_t*)(sm+G1_BL+bo);
                uint32_t bl1=*(const uint32_t*)(sm+G1_BL+bo+16);
                float* c=acc+g*4;
                mma16816(c,ah,bh0,bh1);
                mma16816(c,ah,bl0,bl1);
                mma16816(c,al,bh0,bh1);
            }
        }
    }
    const int r0=n0+mrow0+gid;
#pragma unroll
    for(int kcg=0;kcg<2;kcg++){
        uint32_t h0[8],l0[8],h1[8],l1[8];
#pragma unroll
        for(int q=0;q<8;q++){
            int nt=kcg*8+q;
            int col=ncol0+nt*8+tig*2;
            float ba=g_b2f[col], bb2=g_b2f[col+1];
            float v00=fmaxf(acc[nt*4+0]+ba,0.f), v01=fmaxf(acc[nt*4+1]+bb2,0.f);
            float v10=fmaxf(acc[nt*4+2]+ba,0.f), v11=fmaxf(acc[nt*4+3]+bb2,0.f);
            uint32_t hp=pack2(v00,v01);
            h0[q]=hp;
            l0[q]=pack2(v00-__uint_as_float(hp<<16),v01-__uint_as_float(hp&0xffff0000u));
            hp=pack2(v10,v11);
            h1[q]=hp;
            l1[q]=pack2(v10-__uint_as_float(hp<<16),v11-__uint_as_float(hp&0xffff0000u));
        }
        size_t base0=(size_t)r0*512+(size_t)((ncol0>>6)+kcg)*128+tig*32;
        size_t base1=base0+(size_t)8*512;
        *(uint4*)((char*)g_A2h+base0)=*(uint4*)h0;
        *(uint4*)((char*)g_A2h+base0+16)=*(uint4*)(h0+4);
        *(uint4*)((char*)g_A2l+base0)=*(uint4*)l0;
        *(uint4*)((char*)g_A2l+base0+16)=*(uint4*)(l0+4);
        *(uint4*)((char*)g_A2h+base1)=*(uint4*)h1;
        *(uint4*)((char*)g_A2h+base1+16)=*(uint4*)(h1+4);
        *(uint4*)((char*)g_A2l+base1)=*(uint4*)l1;
        *(uint4*)((char*)g_A2l+base1+16)=*(uint4*)(l1+4);
    }
}

// ------------------- GEMM2 + enc_head (y==2, x<64) -------------------
constexpr int G2_BH0=0, G2_BL0=16128, G2_BH1=32256, G2_BL1=48384;
constexpr int G2_SME=64512;
__global__ void __launch_bounds__(256,2)
k_gemm2(const float* __restrict__ dct2_w,const float* __restrict__ dct2_b,
        const float* __restrict__ fc2_w,const float* __restrict__ fc2_b,
        float* __restrict__ dist_out,float* __restrict__ loss_out){
    extern __shared__ char sm[];
    const int t=threadIdx.x;
    if(blockIdx.y==2){
        if(blockIdx.x>=64) return;
        // enc_head (round-11 body, 256 threads, dyn smem)
        int b=blockIdx.x;
        float* es=(float*)sm;          // 1024 floats
        float* lg=es+E1;               // 36 floats
        for(int j=t;j<E1;j+=256) es[j]=g_e1[(size_t)b*E1+j];
        __syncthreads();
        if(t<LL){
            const float* w=fc2_w+(size_t)t*E1;
            float s=fc2_b[t];
            for(int j=0;j<E1;j++) s+=es[j]*__ldg(w+j);
            lg[t]=s;
        }
        __syncthreads();
        if(t==0){
            float loss=0.f;
            for(int v=0;v<6;v++){
                float mx=-1e30f;
                for(int k=0;k<6;k++) mx=fmaxf(mx,lg[v*6+k]);
                float ex[6],se=0.f;
                for(int k=0;k<6;k++){ex[k]=expf(lg[v*6+k]-mx);se+=ex[k];}
                float inv=1.f/se;
                for(int k=0;k<6;k++){
                    float pp=ex[k]*inv;
                    dist_out[b*LL+v*6+k]=pp;
                    loss+=pp*logf(pp+1e-10f);
                }
            }
            loss_out[b]=0.1f*loss;
        }
        return;
    }
    const int wid=t>>5, lane=t&31, gid=lane>>2, tig=lane&3;
    const int n0=blockIdx.x*128;
    const int s0=blockIdx.y, scnt=blockIdx.y? 3:4;
    float wv[12], b3v[4], dbv[3];
    {
        int ch0=tig*2;
        int chs[4]={ch0,ch0+1,8+ch0,9+ch0};
#pragma unroll
        for(int q=0;q<4;q++){
            b3v[q]=g_b3f[chs[q]];
#pragma unroll
            for(int o=0;o<3;o++) wv[q*3+o]=dct2_w[chs[q]*3+o];
        }
#pragma unroll
        for(int o=0;o<3;o++) dbv[o]=dct2_b[o];
    }
    const int row0=n0+wid*16+gid, row1=row0+8;
    const char* A0h=(const char*)g_A2h+(size_t)row0*512+tig*32;
    const char* A1h=(const char*)g_A2h+(size_t)row1*512+tig*32;
    const char* A0l=(const char*)g_A2l+(size_t)row0*512+tig*32;
    const char* A1l=(const char*)g_A2l+(size_t)row1*512+tig*32;

#define G2_STAGE(S,KC,BUF) do{ \
    int _bh=(BUF)? G2_BH1:G2_BH0, _bl=(BUF)? G2_BL1:G2_BL0; \
    _Pragma("unroll") \
    for(int _i=0;_i<7;_i++){ \
        int _u=_i*256+t; int _kind=_u>=896; int _uu=_kind? _u-896:_u; int _row=_uu>>3,_part=_uu&7; \
        const char* _src=(_kind? (const char*)g_W1nl:(const char*)g_W1nh)+(size_t)((S)*112+_row)*512+(KC)*128+_part*16; \
        cp16(sm+(_kind? _bl:_bh)+_row*144+_part*16,_src); \
    } CP_COMMIT(); }while(0)

    G2_STAGE(s0,0,0);
    CP_WAIT0();
    __syncthreads();
    int cc=0;
    for(int si=0;si<scnt;si++){
        int s=s0+si*2;
        float acc[56];
#pragma unroll
        for(int i=0;i<56;i++) acc[i]=0.f;
        for(int kc=0;kc<4;kc++){
            int buf=cc&1;
            if(cc+1<scnt*4){
                int nn=cc+1, s2=s0+(nn>>2)*2, kc2=nn&3;
                G2_STAGE(s2,kc2,buf^1);
            }
            int bh=buf? G2_BH1:G2_BH0, bl=buf? G2_BL1:G2_BL0;
#pragma unroll
            for(int kh=0;kh<2;kh++){
                uint4 qh=*(const uint4*)(A0h+kc*128+kh*16);
                uint4 rh=*(const uint4*)(A1h+kc*128+kh*16);
                uint4 ql=*(const uint4*)(A0l+kc*128+kh*16);
                uint4 rl=*(const uint4*)(A1l+kc*128+kh*16);
#pragma unroll
                for(int k2=0;k2<2;k2++){
                    const int ks=kh*2+k2;
                    uint32_t ah[4],al[4];
                    if(k2==0){
                        ah[0]=qh.x; ah[1]=rh.x; ah[2]=qh.y; ah[3]=rh.y;
                        al[0]=ql.x; al[1]=rl.x; al[2]=ql.y; al[3]=rl.y;
                    }else{
                        ah[0]=qh.z; ah[1]=rh.z; ah[2]=qh.w; ah[3]=rh.w;
                        al[0]=ql.z; al[1]=rl.z; al[2]=ql.w; al[3]=rl.w;
                    }
#pragma unroll
                    for(int g=0;g<14;g++){
                        int bo=(g*8+gid)*144+ks*32+tig*4;
                        uint32_t bh0=*(const uint32_t*)(sm+bh+bo);
                        uint32_t bh1=*(const uint32_t*)(sm+bh+bo+16);
                        uint32_t bl0=*(const uint32_t*)(sm+bl+bo);
                        uint32_t bl1=*(const uint32_t*)(sm+bl+bo+16);
                        float* c=acc+g*4;
                        mma16816(c,ah,bh0,bh1);
                        mma16816(c,ah,bl0,bl1);
                        mma16816(c,al,bh0,bh1);
                    }
                }
            }
            CP_WAIT0();
            __syncthreads();
            cc++;
        }
#pragma unroll
        for(int hw=0;hw<7;hw++){
            float hA0=fmaxf(acc[hw*8+0]+b3v[0],0.f);
            float hA1=fmaxf(acc[hw*8+1]+b3v[1],0.f);
            float hB0=fmaxf(acc[hw*8+4]+b3v[2],0.f);
            float hB1=fmaxf(acc[hw*8+5]+b3v[3],0.f);
            float hC0=fmaxf(acc[hw*8+2]+b3v[0],0.f);
            float hC1=fmaxf(acc[hw*8+3]+b3v[1],0.f);
            float hD0=fmaxf(acc[hw*8+6]+b3v[2],0.f);
            float hD1=fmaxf(acc[hw*8+7]+b3v[3],0.f);
            float p[6];
#pragma unroll
            for(int o=0;o<3;o++){
                p[o]  =hA0*wv[o]+hA1*wv[3+o]+hB0*wv[6+o]+hB1*wv[9+o];
                p[3+o]=hC0*wv[o]+hC1*wv[3+o]+hD0*wv[6+o]+hD1*wv[9+o];
            }
#pragma unroll
            for(int off=1;off<4;off<<=1)
#pragma unroll
                for(int q=0;q<6;q++) p[q]+=__shfl_xor_sync(0xffffffffu,p[q],off);
            if(tig<3){
                g_em[(size_t)row0*EMP+tig*49+s*7+hw]=p[tig]+dbv[tig];
                g_em[(size_t)row1*EMP+tig*49+s*7+hw]=p[3+tig]+dbv[tig];
            }
        }
    }
#undef G2_STAGE
}

// ------------------- obs: round-11 exact -------------------
constexpr int ONB=96;
constexpr int OBS_SMEM=(ONB*EMP+64*EMP+ONB+64)*4;
__global__ void __launch_bounds__(256,2)
k_obs(const float* __restrict__ x,float* __restrict__ obs){
    extern __shared__ float smf[];
    float* ems=smf;
    float* xs=ems+ONB*EMP;
    float* s2s=xs+64*EMP;
    float* s1s=s2s+ONB;
    const int t=threadIdx.x, n0=blockIdx.x*ONB;
    {
        float4* dst=(float4*)ems;
        const float4* src=(const float4*)(g_em+(size_t)n0*EMP);
        for(int id=t;id<ONB*(EMP/4);id+=256) dst[id]=__ldg(src+id);
    }
    for(int id=t;id<64*F0;id+=256){
        int r=id/F0, c=id-r*F0;
        xs[r*EMP+c]=x[id];
    }
    if(t<64){ xs[t*EMP+F0]=0.f; s1s[t]=g_s1[t]; }
    __syncthreads();
    if(t<ONB){
        const float4* e=(const float4*)(ems+t*EMP);
        float s=0.f;
#pragma unroll 4
        for(int r=0;r<EMP/4;r++){
            float4 v=e[r];
            s+=v.x*v.x+v.y*v.y+v.z*v.z+v.w*v.w;
        }
        s2s[t]=s;
    }
    __syncthreads();
#pragma unroll
    for(int jj=0;jj<2;jj++){
        int tt=t+jj*256;
        if(tt<384){
            int bt=tt/24, nt=tt%24;
            const float4* xp0=(const float4*)(xs+(bt*4+0)*EMP);
            const float4* xp1=(const float4*)(xs+(bt*4+1)*EMP);
            const float4* xp2=(const float4*)(xs+(bt*4+2)*EMP);
            const float4* xp3=(const float4*)(xs+(bt*4+3)*EMP);
            const float4* e0=(const float4*)(ems+(nt*4+0)*EMP);
            const float4* e1=(const float4*)(ems+(nt*4+1)*EMP);
            const float4* e2=(const float4*)(ems+(nt*4+2)*EMP);
            const float4* e3=(const float4*)(ems+(nt*4+3)*EMP);
            float a[16];
#pragma unroll
            for(int i=0;i<16;i++) a[i]=0.f;
            for(int r=0;r<EMP/4;r++){
                float4 xv[4]={xp0[r],xp1[r],xp2[r],xp3[r]};
                float4 ev[4]={e0[r],e1[r],e2[r],e3[r]};
#pragma unroll
                for(int i=0;i<4;i++)
#pragma unroll
                    for(int k=0;k<4;k++)
                        a[i*4+k]+=xv[i].x*ev[k].x+xv[i].y*ev[k].y+xv[i].z*ev[k].z+xv[i].w*ev[k].w;
            }
#pragma unroll
            for(int i=0;i<4;i++){
                int b=bt*4+i;
                float4 o;
                o.x=-0.5f*(s2s[nt*4+0]-2.f*a[i*4+0]+s1s[b]);
                o.y=-0.5f*(s2s[nt*4+1]-2.f*a[i*4+1]+s1s[b]);
                o.z=-0.5f*(s2s[nt*4+2]-2.f*a[i*4+2]+s1s[b]);
                o.w=-0.5f*(s2s[nt*4+3]-2.f*a[i*4+3]+s1s[b]);
                *(float4*)(obs+(size_t)b*NN+n0+nt*4)=o;
            }
        }
    }
}

// ------------------- launch (5 kernels) -------------------
extern "C" void kernel_launch(void* const* d_in,const int* in_sizes,int n_in,
                              void* d_out,int out_size){
    const float* x     =(const float*)d_in[0];
    const float* conv_w=(const float*)d_in[1];
    const float* conv_b=(const float*)d_in[2];
    const float* ebn2_g=(const float*)d_in[3];
    const float* ebn2_b=(const float*)d_in[4];
    const float* fc1_w =(const float*)d_in[5];
    const float* fc1_b =(const float*)d_in[6];
    const float* ebn1_g=(const float*)d_in[7];
    const float* ebn1_b=(const float*)d_in[8];
    const float* fc2_w =(const float*)d_in[9];
    const float* fc2_b =(const float*)d_in[10];
    const float* embeds=(const float*)d_in[11];
    const float* dfc1_w=(const float*)d_in[12];
    const float* dfc1_b=(const float*)d_in[13];
    const float* dbn1_g=(const float*)d_in[14];
    const float* dbn1_b=(const float*)d_in[15];
    const float* dbn1_rm=(const float*)d_in[16];
    const float* dbn1_rv=(const float*)d_in[17];
    const float* dfc2_w=(const float*)d_in[18];
    const float* dfc2_b=(const float*)d_in[19];
    const float* dbn2_g=(const float*)d_in[20];
    const float* dbn2_b=(const float*)d_in[21];
    const float* dbn2_rm=(const float*)d_in[22];
    const float* dbn2_rv=(const float*)d_in[23];
    const float* dct1_w=(const float*)d_in[24];
    const float* dct1_b=(const float*)d_in[25];
    const float* dbn3_g=(const float*)d_in[26];
    const float* dbn3_b=(const float*)d_in[27];
    const float* dbn3_rm=(const float*)d_in[28];
    const float* dbn3_rv=(const float*)d_in[29];
    const float* dct2_w=(const float*)d_in[30];
    const float* dct2_b=(const float*)d_in[31];

    float* out=(float*)d_out;
    float* obs=out;
    float* dist=out+(size_t)Bb*NN;
    float* loss=dist+(size_t)Bb*LL;

    cudaFuncSetAttribute(k_gemm1,cudaFuncAttributeMaxDynamicSharedMemorySize,G1_SME);
    cudaFuncSetAttribute(k_gemm2,cudaFuncAttributeMaxDynamicSharedMemorySize,G2_SME);
    cudaFuncSetAttribute(k_obs,cudaFuncAttributeMaxDynamicSharedMemorySize,OBS_SMEM);

    k_prep<<<256,256>>>(x,embeds,dfc1_w,dfc1_b,dbn1_g,dbn1_b,dbn1_rm,dbn1_rv,
                        dfc2_w,dfc2_b,dbn2_g,dbn2_b,dbn2_rm,dbn2_rv,
                        dct1_w,dct1_b,dbn3_g,dbn3_b,dbn3_rm,dbn3_rv);
    k_prep_pairs<<<172,256>>>(x,conv_w,conv_b,ebn2_g,ebn2_b);
    k_gemm1<<<985,256,G1_SME>>>(fc1_w,fc1_b,ebn1_g,ebn1_b);
    k_gemm2<<<dim3(365,3),256,G2_SME>>>(dct2_w,dct2_b,fc2_w,fc2_b,dist,loss);
    k_obs<<<NN/ONB,256,OBS_SMEM>>>(x,obs);
}